// round 14
// baseline (speedup 1.0000x reference)
#include <cuda_runtime.h>
#include <cuda_bf16.h>
#include <math.h>
#include <stdint.h>

#define D_MODEL 1024
#define NUM_HEADS 16
#define DEPTH 64
#define B_ 4
#define S_ 1024

// ---------------- scratch (static device globals; no allocation) -------------
__device__ float g_wt[(size_t)6 * D_MODEL * D_MODEL];        // W^T fp32
__device__ __nv_bfloat16 g_wth[(size_t)6 * D_MODEL * D_MODEL];
__device__ __nv_bfloat16 g_wtl[(size_t)6 * D_MODEL * D_MODEL];
__device__ __nv_bfloat16 g_qs_h[(size_t)B_ * S_ * D_MODEL], g_qs_l[(size_t)B_ * S_ * D_MODEL];
__device__ __nv_bfloat16 g_ks_h[(size_t)B_ * S_ * D_MODEL], g_ks_l[(size_t)B_ * S_ * D_MODEL];
__device__ __nv_bfloat16 g_vs_h[(size_t)B_ * S_ * D_MODEL], g_vs_l[(size_t)B_ * S_ * D_MODEL];
__device__ __nv_bfloat16 g_pts_h[(size_t)S_ * D_MODEL], g_pts_l[(size_t)S_ * D_MODEL];
__device__ __nv_bfloat16 g_qc_h[(size_t)B_ * S_ * D_MODEL], g_qc_l[(size_t)B_ * S_ * D_MODEL];
__device__ __nv_bfloat16 g_kc_h[(size_t)B_ * S_ * D_MODEL], g_kc_l[(size_t)B_ * S_ * D_MODEL];
__device__ float g_vc[(size_t)B_ * S_ * D_MODEL];
__device__ float g_qp[(size_t)S_ * D_MODEL];
__device__ float g_kp[(size_t)S_ * D_MODEL];
__device__ float g_vtf[(size_t)B_ * NUM_HEADS * DEPTH * S_];
__device__ __nv_bfloat16 g_vt_h[(size_t)B_ * NUM_HEADS * DEPTH * S_];
__device__ __nv_bfloat16 g_vt_l[(size_t)B_ * NUM_HEADS * DEPTH * S_];
__device__ float g_pos[(size_t)NUM_HEADS * S_ * S_];
__device__ __nv_bfloat16 g_ctx_h[(size_t)B_ * S_ * D_MODEL], g_ctx_l[(size_t)B_ * S_ * D_MODEL];

// ============================================================================
// helpers
// ============================================================================
__device__ __forceinline__ uint32_t smem_u32(const void* p) {
    uint32_t a;
    asm("{ .reg .u64 t; cvta.to.shared.u64 t, %1; cvt.u32.u64 %0, t; }" : "=r"(a) : "l"(p));
    return a;
}

__device__ __forceinline__ void ldsm4(uint32_t& r0, uint32_t& r1, uint32_t& r2,
                                      uint32_t& r3, uint32_t addr) {
    asm volatile("ldmatrix.sync.aligned.m8n8.x4.shared.b16 {%0,%1,%2,%3}, [%4];"
                 : "=r"(r0), "=r"(r1), "=r"(r2), "=r"(r3) : "r"(addr));
}

__device__ __forceinline__ void mma16816(float* c, const uint32_t* a, const uint32_t* b) {
    asm volatile("mma.sync.aligned.m16n8k16.row.col.f32.bf16.bf16.f32 "
                 "{%0,%1,%2,%3}, {%4,%5,%6,%7}, {%8,%9}, {%0,%1,%2,%3};"
                 : "+f"(c[0]), "+f"(c[1]), "+f"(c[2]), "+f"(c[3])
                 : "r"(a[0]), "r"(a[1]), "r"(a[2]), "r"(a[3]), "r"(b[0]), "r"(b[1]));
}

__device__ __forceinline__ void split_pair(float x, float y, uint32_t& hi, uint32_t& lo) {
    __nv_bfloat162 h = __floats2bfloat162_rn(x, y);
    float hx = __bfloat162float(h.x);
    float hy = __bfloat162float(h.y);
    __nv_bfloat162 l = __floats2bfloat162_rn(x - hx, y - hy);
    hi = *reinterpret_cast<uint32_t*>(&h);
    lo = *reinterpret_cast<uint32_t*>(&l);
}

__device__ __forceinline__ void split_store(char* sH, char* sL, uint32_t off, float4 v) {
    uint32_t h0, l0, h1, l1;
    split_pair(v.x, v.y, h0, l0);
    split_pair(v.z, v.w, h1, l1);
    *(uint2*)(sH + off) = make_uint2(h0, h1);
    *(uint2*)(sL + off) = make_uint2(l0, l1);
}

#define CP_ASYNC16(dst, src) \
    asm volatile("cp.async.cg.shared.global [%0], [%1], 16;" :: "r"(dst), "l"(src))
#define CP_COMMIT() asm volatile("cp.async.commit_group;")
#define CP_WAIT1()  asm volatile("cp.async.wait_group 1;")
#define CP_WAIT0()  asm volatile("cp.async.wait_group 0;")

// ============================================================================
// split2: fp32 -> bf16 hi/lo, processing float4 units
// ============================================================================
__global__ __launch_bounds__(256)
void split2(const float* __restrict__ in, __nv_bfloat16* __restrict__ hi,
            __nv_bfloat16* __restrict__ lo, int n4) {
    int i = blockIdx.x * 256 + threadIdx.x;
    if (i < n4) {
        float4 v = ((const float4*)in)[i];
        uint32_t h0, l0, h1, l1;
        split_pair(v.x, v.y, h0, l0);
        split_pair(v.z, v.w, h1, l1);
        ((uint2*)hi)[i] = make_uint2(h0, h1);
        ((uint2*)lo)[i] = make_uint2(l0, l1);
    }
}

// ============================================================================
// transposes (fp32)
// ============================================================================
__global__ __launch_bounds__(256)
void transpose1024(const float* __restrict__ in, float* __restrict__ out) {
    __shared__ float t[32][33];
    const int bx = blockIdx.x * 32, by = blockIdx.y * 32;
    const int txx = threadIdx.x, tyy = threadIdx.y;
#pragma unroll
    for (int i = tyy; i < 32; i += 8)
        t[i][txx] = in[(size_t)(by + i) * 1024 + bx + txx];
    __syncthreads();
#pragma unroll
    for (int i = tyy; i < 32; i += 8)
        out[(size_t)(bx + i) * 1024 + by + txx] = t[txx][i];
}

__global__ __launch_bounds__(256)
void transpose_v(const float* __restrict__ vc, float* __restrict__ vt) {
    __shared__ float t[32][33];
    const int bh = blockIdx.z;
    const int b = bh >> 4, h = bh & 15;
    const int s0 = blockIdx.x * 32, d0 = blockIdx.y * 32;
    const int txx = threadIdx.x, tyy = threadIdx.y;
#pragma unroll
    for (int i = tyy; i < 32; i += 8)
        t[i][txx] = vc[((size_t)b * S_ + s0 + i) * D_MODEL + h * DEPTH + d0 + txx];
    __syncthreads();
#pragma unroll
    for (int i = tyy; i < 32; i += 8)
        vt[(size_t)bh * DEPTH * S_ + (size_t)(d0 + i) * S_ + s0 + txx] = t[txx][i];
}

// ============================================================================
// proj_pre: pipelined bf16x3 GEMM, preconverted operands.
// out[M,1024] = A @ W + bias (A,W given as bf16 hi/lo; Wt = W^T layout).
// 128x128 tile, BK=32 halves, 3-stage cp.async. 256 threads, 120 KB SMEM.
// SPLIT: write bf16 hi/lo outputs instead of fp32.
// ============================================================================
#define PP_STAGE 40960
#define PP_SMEM (3 * PP_STAGE)

template <bool SPLIT>
__global__ __launch_bounds__(256, 1)
void proj_pre(const __nv_bfloat16* __restrict__ Ah, const __nv_bfloat16* __restrict__ Al,
              const __nv_bfloat16* __restrict__ Bh, const __nv_bfloat16* __restrict__ Bl,
              const float* __restrict__ bias,
              float* __restrict__ outf,
              __nv_bfloat16* __restrict__ outh, __nv_bfloat16* __restrict__ outl)
{
    extern __shared__ char sm[];
    const uint32_t smb = smem_u32(sm);

    const int tid = threadIdx.x;
    const int lane = tid & 31, wid = tid >> 5;
    const int warp_n = wid & 3, warp_m = wid >> 2;
    const int m0 = blockIdx.y * 128, n0 = blockIdx.x * 128;

    // each thread loads 8x16B for ONE of the 4 arrays, 2 consecutive rows
    const int arr = tid >> 6;           // 0:Ah 1:Al 2:Bh 3:Bl
    const int rloc = (tid & 63) * 2;    // rows rloc, rloc+1
    const __nv_bfloat16* gbase =
        (arr == 0) ? Ah + (size_t)m0 * 1024 :
        (arr == 1) ? Al + (size_t)m0 * 1024 :
        (arr == 2) ? Bh + (size_t)n0 * 1024 :
                     Bl + (size_t)n0 * 1024;
    const __nv_bfloat16* grow = gbase + (size_t)rloc * 1024;
    const uint32_t sarr = (uint32_t)arr * 10240u + (uint32_t)rloc * 80u;

    float acc[64];
#pragma unroll
    for (int i = 0; i < 64; i++) acc[i] = 0.0f;

    const uint32_t a_off =
        (uint32_t)((warp_m * 64 + (lane & 7) + ((lane >> 3) & 1) * 8) * 80 + (lane >> 4) * 16);
    const uint32_t b_off =
        (uint32_t)((warp_n * 32 + (lane & 7) + ((lane >> 4) & 1) * 8) * 80 + ((lane >> 3) & 1) * 16);

    // prologue: stages 0,1
#pragma unroll
    for (int pre = 0; pre < 2; pre++) {
        const uint32_t stb = smb + (uint32_t)pre * PP_STAGE + sarr;
        const __nv_bfloat16* g = grow + pre * 32;
#pragma unroll
        for (int rr = 0; rr < 2; rr++)
#pragma unroll
            for (int ch = 0; ch < 4; ch++)
                CP_ASYNC16(stb + (uint32_t)rr * 80u + (uint32_t)ch * 16u,
                           g + (size_t)rr * 1024 + ch * 8);
        CP_COMMIT();
    }

    for (int it = 0; it < 32; ++it) {
        CP_WAIT1();
        __syncthreads();

        if (it + 2 < 32) {
            const uint32_t stb = smb + (uint32_t)((it + 2) % 3) * PP_STAGE + sarr;
            const __nv_bfloat16* g = grow + (it + 2) * 32;
#pragma unroll
            for (int rr = 0; rr < 2; rr++)
#pragma unroll
                for (int ch = 0; ch < 4; ch++)
                    CP_ASYNC16(stb + (uint32_t)rr * 80u + (uint32_t)ch * 16u,
                               g + (size_t)rr * 1024 + ch * 8);
            CP_COMMIT();
        }

        const uint32_t stb = smb + (uint32_t)(it % 3) * PP_STAGE;
        const uint32_t pAh = stb, pAl = stb + 10240u, pBh = stb + 20480u, pBl = stb + 30720u;

#pragma unroll
        for (int ks = 0; ks < 2; ++ks) {
            const uint32_t ko = (uint32_t)(ks * 32);
            uint32_t ah[4][4], bh[4][2];
#pragma unroll
            for (int mt = 0; mt < 4; mt++)
                ldsm4(ah[mt][0], ah[mt][1], ah[mt][2], ah[mt][3],
                      pAh + a_off + (uint32_t)(mt * 16 * 80) + ko);
#pragma unroll
            for (int p = 0; p < 2; p++) {
                uint32_t t0, t1, t2, t3;
                ldsm4(t0, t1, t2, t3, pBh + b_off + (uint32_t)(p * 16 * 80) + ko);
                bh[2 * p][0] = t0; bh[2 * p][1] = t1;
                bh[2 * p + 1][0] = t2; bh[2 * p + 1][1] = t3;
            }
#pragma unroll
            for (int mt = 0; mt < 4; mt++)
#pragma unroll
                for (int nt = 0; nt < 4; nt++)
                    mma16816(acc + (mt * 4 + nt) * 4, ah[mt], bh[nt]);

            uint32_t bl[4][2];
#pragma unroll
            for (int p = 0; p < 2; p++) {
                uint32_t t0, t1, t2, t3;
                ldsm4(t0, t1, t2, t3, pBl + b_off + (uint32_t)(p * 16 * 80) + ko);
                bl[2 * p][0] = t0; bl[2 * p][1] = t1;
                bl[2 * p + 1][0] = t2; bl[2 * p + 1][1] = t3;
            }
#pragma unroll
            for (int mt = 0; mt < 4; mt++)
#pragma unroll
                for (int nt = 0; nt < 4; nt++)
                    mma16816(acc + (mt * 4 + nt) * 4, ah[mt], bl[nt]);

            uint32_t al[4][4];
#pragma unroll
            for (int mt = 0; mt < 4; mt++)
                ldsm4(al[mt][0], al[mt][1], al[mt][2], al[mt][3],
                      pAl + a_off + (uint32_t)(mt * 16 * 80) + ko);
#pragma unroll
            for (int mt = 0; mt < 4; mt++)
#pragma unroll
                for (int nt = 0; nt < 4; nt++)
                    mma16816(acc + (mt * 4 + nt) * 4, al[mt], bh[nt]);
        }
    }
    CP_WAIT0();

    const int rbase = m0 + warp_m * 64 + (lane >> 2);
    const int cbase = n0 + warp_n * 32 + (lane & 3) * 2;
#pragma unroll
    for (int mt = 0; mt < 4; mt++)
#pragma unroll
        for (int nt = 0; nt < 4; nt++) {
            const float* a = acc + (mt * 4 + nt) * 4;
            const int r = rbase + mt * 16;
            const int c = cbase + nt * 8;
            float2 b2 = *(const float2*)(bias + c);
            float v0 = a[0] + b2.x, v1 = a[1] + b2.y;
            float v2 = a[2] + b2.x, v3 = a[3] + b2.y;
            if (SPLIT) {
                uint32_t hi, lo;
                split_pair(v0, v1, hi, lo);
                *(uint32_t*)(outh + (size_t)r * 1024 + c) = hi;
                *(uint32_t*)(outl + (size_t)r * 1024 + c) = lo;
                split_pair(v2, v3, hi, lo);
                *(uint32_t*)(outh + (size_t)(r + 8) * 1024 + c) = hi;
                *(uint32_t*)(outl + (size_t)(r + 8) * 1024 + c) = lo;
            } else {
                *(float2*)(outf + (size_t)r * 1024 + c) = make_float2(v0, v1);
                *(float2*)(outf + (size_t)(r + 8) * 1024 + c) = make_float2(v2, v3);
            }
        }
}

// ============================================================================
// gemm_bf16x3 (fp32-in core) — kept for pos_mma (K=64, cheap)
// ============================================================================
template <int BN>
__device__ __forceinline__ void gemm_bf16x3(
    const float* __restrict__ A, int lda, int m0,
    const float* __restrict__ Bt, int ldb, int n0,
    int kIters, float* __restrict__ acc)
{
    constexpr int NWN = BN / 32;
    constexpr int NWM = 8 / NWN;
    constexpr int WROWS = 128 / NWM;
    constexpr int MT = WROWS / 16;

    __shared__ __align__(16) __nv_bfloat16 sAh[128][24];
    __shared__ __align__(16) __nv_bfloat16 sAl[128][24];
    __shared__ __align__(16) __nv_bfloat16 sBh[BN][24];
    __shared__ __align__(16) __nv_bfloat16 sBl[BN][24];

    const int tid = threadIdx.x;
    const int lane = tid & 31;
    const int wid = tid >> 5;
    const int warp_n = wid % NWN;
    const int warp_m = wid / NWN;

    const int row0 = tid >> 2;
    const int c0 = tid & 3;

    const float* ApA = A + (size_t)(m0 + row0) * lda + c0 * 4;
    const float* ApB = ApA + (size_t)64 * lda;
    const float* BpA = Bt + (size_t)(n0 + row0) * ldb + c0 * 4;
    const float* BpB = BpA + (size_t)64 * ldb;

    const uint32_t stA = (uint32_t)row0 * 48u + (uint32_t)c0 * 8u;
    const uint32_t stB = stA + 64u * 48u;

    const uint32_t baseAh = smem_u32(sAh);
    const uint32_t baseAl = smem_u32(sAl);
    const uint32_t baseBh = smem_u32(sBh);
    const uint32_t baseBl = smem_u32(sBl);

    const uint32_t a_off =
        (uint32_t)((warp_m * WROWS + (lane & 7) + ((lane >> 3) & 1) * 8) * 48 +
                   (lane >> 4) * 16);
    const uint32_t b_off =
        (uint32_t)((warp_n * 32 + (lane & 7) + ((lane >> 4) & 1) * 8) * 48 +
                   ((lane >> 3) & 1) * 16);

    float4 ra0 = *(const float4*)ApA;
    float4 ra1 = *(const float4*)ApB;
    float4 rb0 = *(const float4*)BpA;
    float4 rb1 = make_float4(0.f, 0.f, 0.f, 0.f);
    if (BN == 128) rb1 = *(const float4*)BpB;

    for (int it = 0; it < kIters; ++it) {
        __syncthreads();
        split_store((char*)sAh, (char*)sAl, stA, ra0);
        split_store((char*)sAh, (char*)sAl, stB, ra1);
        split_store((char*)sBh, (char*)sBl, stA, rb0);
        if (BN == 128) split_store((char*)sBh, (char*)sBl, stB, rb1);
        __syncthreads();

        if (it + 1 < kIters) {
            const int ko = (it + 1) * 16;
            ra0 = *(const float4*)(ApA + ko);
            ra1 = *(const float4*)(ApB + ko);
            rb0 = *(const float4*)(BpA + ko);
            if (BN == 128) rb1 = *(const float4*)(BpB + ko);
        }

        uint32_t ah[MT][4], bh[4][2];
#pragma unroll
        for (int mt = 0; mt < MT; mt++)
            ldsm4(ah[mt][0], ah[mt][1], ah[mt][2], ah[mt][3],
                  baseAh + a_off + (uint32_t)(mt * 16 * 48));
#pragma unroll
        for (int p = 0; p < 2; p++) {
            uint32_t t0, t1, t2, t3;
            ldsm4(t0, t1, t2, t3, baseBh + b_off + (uint32_t)(p * 16 * 48));
            bh[2 * p][0] = t0; bh[2 * p][1] = t1;
            bh[2 * p + 1][0] = t2; bh[2 * p + 1][1] = t3;
        }
#pragma unroll
        for (int mt = 0; mt < MT; mt++)
#pragma unroll
            for (int nt = 0; nt < 4; nt++)
                mma16816(acc + (mt * 4 + nt) * 4, ah[mt], bh[nt]);

        uint32_t bl[4][2];
#pragma unroll
        for (int p = 0; p < 2; p++) {
            uint32_t t0, t1, t2, t3;
            ldsm4(t0, t1, t2, t3, baseBl + b_off + (uint32_t)(p * 16 * 48));
            bl[2 * p][0] = t0; bl[2 * p][1] = t1;
            bl[2 * p + 1][0] = t2; bl[2 * p + 1][1] = t3;
        }
#pragma unroll
        for (int mt = 0; mt < MT; mt++)
#pragma unroll
            for (int nt = 0; nt < 4; nt++)
                mma16816(acc + (mt * 4 + nt) * 4, ah[mt], bl[nt]);

        uint32_t al[MT][4];
#pragma unroll
        for (int mt = 0; mt < MT; mt++)
            ldsm4(al[mt][0], al[mt][1], al[mt][2], al[mt][3],
                  baseAl + a_off + (uint32_t)(mt * 16 * 48));
#pragma unroll
        for (int mt = 0; mt < MT; mt++)
#pragma unroll
            for (int nt = 0; nt < 4; nt++)
                mma16816(acc + (mt * 4 + nt) * 4, al[mt], bh[nt]);
    }
}

// ============================================================================
// pos scores: pos[h] = q_p @ k_p^T with theta patches; K=64 (fp32 in, fp32 out)
// ============================================================================
__global__ __launch_bounds__(256, 1)
void pos_mma(const float* __restrict__ qp, const float* __restrict__ kp,
             const float* __restrict__ tcc, const float* __restrict__ tco,
             const float* __restrict__ toc, float* __restrict__ pos)
{
    const int h = blockIdx.z;
    float acc[64];
#pragma unroll
    for (int i = 0; i < 64; i++) acc[i] = 0.0f;
    const int m0 = blockIdx.y * 128, n0 = blockIdx.x * 128;
    gemm_bf16x3<128>(qp + h * DEPTH, 1024, m0, kp + h * DEPTH, 1024, n0, 4, acc);

    const float thcc = tcc[h], thco = tco[h], thoc = toc[h];
    float* O = pos + (size_t)h * S_ * S_;

    const int lane = threadIdx.x & 31, wid = threadIdx.x >> 5;
    const int warp_n = wid & 3, warp_m = wid >> 2;
    const int rbase = m0 + warp_m * 64 + (lane >> 2);
    const int cbase = n0 + warp_n * 32 + (lane & 3) * 2;
#pragma unroll
    for (int mt = 0; mt < 4; mt++)
#pragma unroll
        for (int nt = 0; nt < 4; nt++) {
            const float* a = acc + (mt * 4 + nt) * 4;
            const int r = rbase + mt * 16;
            const int c = cbase + nt * 8;
            float v0 = a[0], v1 = a[1], v2 = a[2], v3 = a[3];
            if (r == 0) { v0 = (c == 0) ? thcc : thco; v1 = thco; }
            else if (c == 0) v0 = thoc;
            if (c == 0) v2 = thoc;
            *(float2*)(O + (size_t)r * 1024 + c) = make_float2(v0, v1);
            *(float2*)(O + (size_t)(r + 8) * 1024 + c) = make_float2(v2, v3);
        }
}

// ============================================================================
// Fused flash attention (preconverted bf16 hi/lo inputs, split ctx output)
// ============================================================================
#define QK_STRIDE 144
#define VT_STRIDE 272
#define QH_OFF 0
#define QL_OFF 18432
#define KH_OFF 36864
#define KL_OFF 55296
#define VH_OFF 73728
#define VL_OFF 91136
#define RS_OFF 108544
#define FLASH_SMEM 110592

__global__ __launch_bounds__(256, 1)
void flash_attn(const __nv_bfloat16* __restrict__ qch, const __nv_bfloat16* __restrict__ qcl,
                const __nv_bfloat16* __restrict__ kch, const __nv_bfloat16* __restrict__ kcl,
                const __nv_bfloat16* __restrict__ vth, const __nv_bfloat16* __restrict__ vtl,
                const float* __restrict__ pos,
                __nv_bfloat16* __restrict__ ctxh, __nv_bfloat16* __restrict__ ctxl)
{
    extern __shared__ char sm[];
    char* qh = sm + QH_OFF;  char* ql = sm + QL_OFF;
    char* kh = sm + KH_OFF;  char* kl = sm + KL_OFF;  // reused as P hi/lo
    char* vh = sm + VH_OFF;  char* vl = sm + VL_OFF;
    float* rsum_sm = (float*)(sm + RS_OFF);

    const int bh = blockIdx.y;
    const int b = bh >> 4, h = bh & 15;
    const int m0 = blockIdx.x * 128;

    const int tid = threadIdx.x;
    const int lane = tid & 31;
    const int wid = tid >> 5;
    const int warp_m = wid >> 2;
    const int warp_n = wid & 3;

    const __nv_bfloat16* Qh = qch + ((size_t)b * S_ + m0) * D_MODEL + h * DEPTH;
    const __nv_bfloat16* Ql = qcl + ((size_t)b * S_ + m0) * D_MODEL + h * DEPTH;
    const __nv_bfloat16* Kh = kch + (size_t)b * S_ * D_MODEL + h * DEPTH;
    const __nv_bfloat16* Kl = kcl + (size_t)b * S_ * D_MODEL + h * DEPTH;
    const __nv_bfloat16* Vh = vth + (size_t)bh * DEPTH * S_;
    const __nv_bfloat16* Vl = vtl + (size_t)bh * DEPTH * S_;
    const float* Pb = pos + (size_t)h * S_ * S_;

    const uint32_t qh_b = smem_u32(qh), ql_b = smem_u32(ql);
    const uint32_t kh_b = smem_u32(kh), kl_b = smem_u32(kl);
    const uint32_t vh_b = smem_u32(vh), vl_b = smem_u32(vl);

    const int row0 = tid >> 2;   // 0..63
    const int c0 = tid & 3;

    // ---- load Q tile once (bf16 hi/lo, 64 halves/row = 128 B) ----
#pragma unroll
    for (int rr = 0; rr < 2; rr++) {
        const int r = row0 + rr * 64;
        uint4 t0 = *(const uint4*)(Qh + (size_t)r * 1024 + c0 * 16);
        uint4 t1 = *(const uint4*)(Qh + (size_t)r * 1024 + c0 * 16 + 8);
        *(uint4*)(qh + r * QK_STRIDE + c0 * 32) = t0;
        *(uint4*)(qh + r * QK_STRIDE + c0 * 32 + 16) = t1;
        t0 = *(const uint4*)(Ql + (size_t)r * 1024 + c0 * 16);
        t1 = *(const uint4*)(Ql + (size_t)r * 1024 + c0 * 16 + 8);
        *(uint4*)(ql + r * QK_STRIDE + c0 * 32) = t0;
        *(uint4*)(ql + r * QK_STRIDE + c0 * 32 + 16) = t1;
    }

    const uint32_t a_off =
        (uint32_t)((warp_m * 64 + (lane & 7) + ((lane >> 3) & 1) * 8) * QK_STRIDE +
                   (lane >> 4) * 16);
    const uint32_t b_off =
        (uint32_t)((warp_n * 32 + (lane & 7) + ((lane >> 4) & 1) * 8) * QK_STRIDE +
                   ((lane >> 3) & 1) * 16);
    const uint32_t bv_off =
        (uint32_t)((warp_n * 16 + (lane & 7) + ((lane >> 4) & 1) * 8) * VT_STRIDE +
                   ((lane >> 3) & 1) * 16);

    const int rbase = warp_m * 64 + (lane >> 2);
    const int cbase = warp_n * 32 + (lane & 3) * 2;
    const int khalf = warp_n >> 1;
    const int clocal = (warp_n & 1) * 32 + (lane & 3) * 2;

    float oacc[32];
#pragma unroll
    for (int i = 0; i < 32; i++) oacc[i] = 0.0f;
    float rs[8];
#pragma unroll
    for (int i = 0; i < 8; i++) rs[i] = 0.0f;

    for (int j = 0; j < 8; ++j) {
        __syncthreads();

        // ---- load K chunk [128x64] hi/lo + Vt chunk [64x128] hi/lo ----
#pragma unroll
        for (int rr = 0; rr < 2; rr++) {
            const int r = row0 + rr * 64;
            const size_t gr = (size_t)(j * 128 + r) * 1024;
            uint4 t0 = *(const uint4*)(Kh + gr + c0 * 16);
            uint4 t1 = *(const uint4*)(Kh + gr + c0 * 16 + 8);
            *(uint4*)(kh + r * QK_STRIDE + c0 * 32) = t0;
            *(uint4*)(kh + r * QK_STRIDE + c0 * 32 + 16) = t1;
            t0 = *(const uint4*)(Kl + gr + c0 * 16);
            t1 = *(const uint4*)(Kl + gr + c0 * 16 + 8);
            *(uint4*)(kl + r * QK_STRIDE + c0 * 32) = t0;
            *(uint4*)(kl + r * QK_STRIDE + c0 * 32 + 16) = t1;
        }
#pragma unroll
        for (int cc = 0; cc < 4; cc++) {
            const size_t gv = (size_t)row0 * S_ + j * 128 + c0 * 32 + cc * 8;
            uint4 t = *(const uint4*)(Vh + gv);
            *(uint4*)(vh + row0 * VT_STRIDE + c0 * 64 + cc * 16) = t;
            t = *(const uint4*)(Vl + gv);
            *(uint4*)(vl + row0 * VT_STRIDE + c0 * 64 + cc * 16) = t;
        }
        __syncthreads();

        // ---- S block: 128x128 = Q . K^T (bf16x3) ----
        float sacc[64];
#pragma unroll
        for (int i = 0; i < 64; i++) sacc[i] = 0.0f;

        for (int ki = 0; ki < 4; ++ki) {
            const uint32_t ko = (uint32_t)(ki * 32);
            uint32_t ah[4][4], bhf[4][2];
#pragma unroll
            for (int mt = 0; mt < 4; mt++)
                ldsm4(ah[mt][0], ah[mt][1], ah[mt][2], ah[mt][3],
                      qh_b + a_off + (uint32_t)(mt * 16 * QK_STRIDE) + ko);
#pragma unroll
            for (int p = 0; p < 2; p++) {
                uint32_t t0, t1, t2, t3;
                ldsm4(t0, t1, t2, t3, kh_b + b_off + (uint32_t)(p * 16 * QK_STRIDE) + ko);
                bhf[2 * p][0] = t0; bhf[2 * p][1] = t1;
                bhf[2 * p + 1][0] = t2; bhf[2 * p + 1][1] = t3;
            }
#pragma unroll
            for (int mt = 0; mt < 4; mt++)
#pragma unroll
                for (int nt = 0; nt < 4; nt++)
                    mma16816(sacc + (mt * 4 + nt) * 4, ah[mt], bhf[nt]);

            uint32_t blf[4][2];
#pragma unroll
            for (int p = 0; p < 2; p++) {
                uint32_t t0, t1, t2, t3;
                ldsm4(t0, t1, t2, t3, kl_b + b_off + (uint32_t)(p * 16 * QK_STRIDE) + ko);
                blf[2 * p][0] = t0; blf[2 * p][1] = t1;
                blf[2 * p + 1][0] = t2; blf[2 * p + 1][1] = t3;
            }
#pragma unroll
            for (int mt = 0; mt < 4; mt++)
#pragma unroll
                for (int nt = 0; nt < 4; nt++)
                    mma16816(sacc + (mt * 4 + nt) * 4, ah[mt], blf[nt]);

            uint32_t al[4][4];
#pragma unroll
            for (int mt = 0; mt < 4; mt++)
                ldsm4(al[mt][0], al[mt][1], al[mt][2], al[mt][3],
                      ql_b + a_off + (uint32_t)(mt * 16 * QK_STRIDE) + ko);
#pragma unroll
            for (int mt = 0; mt < 4; mt++)
#pragma unroll
                for (int nt = 0; nt < 4; nt++)
                    mma16816(sacc + (mt * 4 + nt) * 4, al[mt], bhf[nt]);
        }

        // ---- epilogue: p = exp((s + pos) * 0.125); accumulate row sums ----
#pragma unroll
        for (int mt = 0; mt < 4; mt++) {
            const int r = rbase + mt * 16;
#pragma unroll
            for (int nt = 0; nt < 4; nt++) {
                float* a = sacc + (mt * 4 + nt) * 4;
                const int cg = j * 128 + cbase + nt * 8;
                float2 p0 = *(const float2*)(Pb + (size_t)(m0 + r) * 1024 + cg);
                float2 p1 = *(const float2*)(Pb + (size_t)(m0 + r + 8) * 1024 + cg);
                a[0] = __expf((a[0] + p0.x) * 0.125f);
                a[1] = __expf((a[1] + p0.y) * 0.125f);
                a[2] = __expf((a[2] + p1.x) * 0.125f);
                a[3] = __expf((a[3] + p1.y) * 0.125f);
                rs[mt * 2 + 0] += a[0] + a[1];
                rs[mt * 2 + 1] += a[2] + a[3];
            }
        }

        // ---- two k-halves: store P half, then PV mma ----
#pragma unroll
        for (int half = 0; half < 2; ++half) {
            __syncthreads();
            if (khalf == half) {
#pragma unroll
                for (int mt = 0; mt < 4; mt++) {
                    const int r = rbase + mt * 16;
#pragma unroll
                    for (int nt = 0; nt < 4; nt++) {
                        float* a = sacc + (mt * 4 + nt) * 4;
                        const uint32_t co = (uint32_t)(clocal + nt * 8) * 2u;
                        uint32_t hi, lo;
                        split_pair(a[0], a[1], hi, lo);
                        *(uint32_t*)(kh + (uint32_t)r * QK_STRIDE + co) = hi;
                        *(uint32_t*)(kl + (uint32_t)r * QK_STRIDE + co) = lo;
                        split_pair(a[2], a[3], hi, lo);
                        *(uint32_t*)(kh + (uint32_t)(r + 8) * QK_STRIDE + co) = hi;
                        *(uint32_t*)(kl + (uint32_t)(r + 8) * QK_STRIDE + co) = lo;
                    }
                }
            }
            __syncthreads();

            const uint32_t vcol = (uint32_t)(half * 128);
            for (int ki = 0; ki < 4; ++ki) {
                const uint32_t ko = (uint32_t)(ki * 32);
                uint32_t pa[4][4], vbh[2][2], vbl[2][2];
#pragma unroll
                for (int mt = 0; mt < 4; mt++)
                    ldsm4(pa[mt][0], pa[mt][1], pa[mt][2], pa[mt][3],
                          kh_b + a_off + (uint32_t)(mt * 16 * QK_STRIDE) + ko);
                {
                    uint32_t t0, t1, t2, t3;
                    ldsm4(t0, t1, t2, t3, vh_b + bv_off + vcol + ko);
                    vbh[0][0] = t0; vbh[0][1] = t1; vbh[1][0] = t2; vbh[1][1] = t3;
                    ldsm4(t0, t1, t2, t3, vl_b + bv_off + vcol + ko);
                    vbl[0][0] = t0; vbl[0][1] = t1; vbl[1][0] = t2; vbl[1][1] = t3;
                }
#pragma unroll
                for (int mt = 0; mt < 4; mt++)
#pragma unroll
                    for (int nt = 0; nt < 2; nt++) {
                        mma16816(oacc + (mt * 2 + nt) * 4, pa[mt], vbh[nt]);
                        mma16816(oacc + (mt * 2 + nt) * 4, pa[mt], vbl[nt]);
                    }
                uint32_t pl[4][4];
#pragma unroll
                for (int mt = 0; mt < 4; mt++)
                    ldsm4(pl[mt][0], pl[mt][1], pl[mt][2], pl[mt][3],
                          kl_b + a_off + (uint32_t)(mt * 16 * QK_STRIDE) + ko);
#pragma unroll
                for (int mt = 0; mt < 4; mt++)
#pragma unroll
                    for (int nt = 0; nt < 2; nt++)
                        mma16816(oacc + (mt * 2 + nt) * 4, pl[mt], vbh[nt]);
            }
        }
    }

    // ---- row-sum reduce + normalize + split-write ctx ----
#pragma unroll
    for (int i = 0; i < 8; i++) {
        rs[i] += __shfl_xor_sync(0xffffffffu, rs[i], 1);
        rs[i] += __shfl_xor_sync(0xffffffffu, rs[i], 2);
    }
    if ((lane & 3) == 0) {
#pragma unroll
        for (int mt = 0; mt < 4; mt++) {
            rsum_sm[warp_n * 128 + rbase + mt * 16] = rs[mt * 2 + 0];
            rsum_sm[warp_n * 128 + rbase + mt * 16 + 8] = rs[mt * 2 + 1];
        }
    }
    __syncthreads();

    const size_t obase = ((size_t)b * S_ + m0) * D_MODEL + h * DEPTH;
    const int cob = warp_n * 16 + (lane & 3) * 2;
#pragma unroll
    for (int mt = 0; mt < 4; mt++) {
        const int r = rbase + mt * 16;
        const float inv0 = 1.0f / (rsum_sm[r] + rsum_sm[128 + r] +
                                   rsum_sm[256 + r] + rsum_sm[384 + r]);
        const float inv1 = 1.0f / (rsum_sm[r + 8] + rsum_sm[128 + r + 8] +
                                   rsum_sm[256 + r + 8] + rsum_sm[384 + r + 8]);
#pragma unroll
        for (int nt = 0; nt < 2; nt++) {
            const float* a = oacc + (mt * 2 + nt) * 4;
            const int c = cob + nt * 8;
            uint32_t hi, lo;
            split_pair(a[0] * inv0, a[1] * inv0, hi, lo);
            *(uint32_t*)(ctxh + obase + (size_t)r * 1024 + c) = hi;
            *(uint32_t*)(ctxl + obase + (size_t)r * 1024 + c) = lo;
            split_pair(a[2] * inv1, a[3] * inv1, hi, lo);
            *(uint32_t*)(ctxh + obase + (size_t)(r + 8) * 1024 + c) = hi;
            *(uint32_t*)(ctxl + obase + (size_t)(r + 8) * 1024 + c) = lo;
        }
    }
}

// ============================================================================
// kernel_launch
// ============================================================================
extern "C" void kernel_launch(void* const* d_in, const int* in_sizes, int n_in,
                              void* d_out, int out_size)
{
    (void)in_sizes; (void)n_in; (void)out_size;

    const float* q   = (const float*)d_in[0];
    const float* k   = (const float*)d_in[1];
    const float* v   = (const float*)d_in[2];
    const float* Wq  = (const float*)d_in[3];
    const float* bq  = (const float*)d_in[4];
    const float* Wk  = (const float*)d_in[5];
    const float* bk  = (const float*)d_in[6];
    const float* Wv  = (const float*)d_in[7];
    const float* bv  = (const float*)d_in[8];
    const float* Uq  = (const float*)d_in[9];
    const float* buq = (const float*)d_in[10];
    const float* Uk  = (const float*)d_in[11];
    const float* buk = (const float*)d_in[12];
    const float* pt  = (const float*)d_in[13];
    const float* tcc = (const float*)d_in[14];
    const float* tco = (const float*)d_in[15];
    const float* toc = (const float*)d_in[16];
    const float* Wo  = (const float*)d_in[17];
    const float* bo  = (const float*)d_in[18];
    float* out = (float*)d_out;

    float *wt, *vc, *qp, *kp, *vtf, *pos;
    __nv_bfloat16 *wth, *wtl, *qsh, *qsl, *ksh, *ksl, *vsh, *vsl, *ptsh, *ptsl;
    __nv_bfloat16 *qch, *qcl, *kch, *kcl, *vth, *vtl, *cxh, *cxl;
    cudaGetSymbolAddress((void**)&wt, g_wt);
    cudaGetSymbolAddress((void**)&wth, g_wth);
    cudaGetSymbolAddress((void**)&wtl, g_wtl);
    cudaGetSymbolAddress((void**)&qsh, g_qs_h); cudaGetSymbolAddress((void**)&qsl, g_qs_l);
    cudaGetSymbolAddress((void**)&ksh, g_ks_h); cudaGetSymbolAddress((void**)&ksl, g_ks_l);
    cudaGetSymbolAddress((void**)&vsh, g_vs_h); cudaGetSymbolAddress((void**)&vsl, g_vs_l);
    cudaGetSymbolAddress((void**)&ptsh, g_pts_h); cudaGetSymbolAddress((void**)&ptsl, g_pts_l);
    cudaGetSymbolAddress((void**)&qch, g_qc_h); cudaGetSymbolAddress((void**)&qcl, g_qc_l);
    cudaGetSymbolAddress((void**)&kch, g_kc_h); cudaGetSymbolAddress((void**)&kcl, g_kc_l);
    cudaGetSymbolAddress((void**)&vc, g_vc);
    cudaGetSymbolAddress((void**)&qp, g_qp);
    cudaGetSymbolAddress((void**)&kp, g_kp);
    cudaGetSymbolAddress((void**)&vtf, g_vtf);
    cudaGetSymbolAddress((void**)&vth, g_vt_h); cudaGetSymbolAddress((void**)&vtl, g_vt_l);
    cudaGetSymbolAddress((void**)&pos, g_pos);
    cudaGetSymbolAddress((void**)&cxh, g_ctx_h); cudaGetSymbolAddress((void**)&cxl, g_ctx_l);

    cudaFuncSetAttribute(proj_pre<true>,
                         cudaFuncAttributeMaxDynamicSharedMemorySize, PP_SMEM);
    cudaFuncSetAttribute(proj_pre<false>,
                         cudaFuncAttributeMaxDynamicSharedMemorySize, PP_SMEM);
    cudaFuncSetAttribute(flash_attn,
                         cudaFuncAttributeMaxDynamicSharedMemorySize, FLASH_SMEM);

    const size_t WSZ = (size_t)D_MODEL * D_MODEL;
    const dim3 tgrid(32, 32), tblk(32, 8);
    const int N4_ACT = (B_ * S_ * D_MODEL) / 4;      // 1M float4
    const int N4_PT  = (S_ * D_MODEL) / 4;           // 256K
    const int N4_W6  = (int)((6 * WSZ) / 4);

    // weights: transpose then split
    transpose1024<<<tgrid, tblk>>>(Wq, wt + 0 * WSZ);
    transpose1024<<<tgrid, tblk>>>(Wk, wt + 1 * WSZ);
    transpose1024<<<tgrid, tblk>>>(Wv, wt + 2 * WSZ);
    transpose1024<<<tgrid, tblk>>>(Uq, wt + 3 * WSZ);
    transpose1024<<<tgrid, tblk>>>(Uk, wt + 4 * WSZ);
    transpose1024<<<tgrid, tblk>>>(Wo, wt + 5 * WSZ);
    split2<<<(N4_W6 + 255) / 256, 256>>>(wt, wth, wtl, N4_W6);

    // activations: split
    split2<<<(N4_ACT + 255) / 256, 256>>>(q, qsh, qsl, N4_ACT);
    split2<<<(N4_ACT + 255) / 256, 256>>>(k, ksh, ksl, N4_ACT);
    split2<<<(N4_ACT + 255) / 256, 256>>>(v, vsh, vsl, N4_ACT);
    split2<<<(N4_PT + 255) / 256, 256>>>(pt, ptsh, ptsl, N4_PT);

    // projections (pipelined bf16x3)
    proj_pre<true><<<dim3(8, 32), 256, PP_SMEM>>>(qsh, qsl, wth + 0 * WSZ, wtl + 0 * WSZ,
                                                  bq, nullptr, qch, qcl);
    proj_pre<true><<<dim3(8, 32), 256, PP_SMEM>>>(ksh, ksl, wth + 1 * WSZ, wtl + 1 * WSZ,
                                                  bk, nullptr, kch, kcl);
    proj_pre<false><<<dim3(8, 32), 256, PP_SMEM>>>(vsh, vsl, wth + 2 * WSZ, wtl + 2 * WSZ,
                                                   bv, vc, nullptr, nullptr);
    proj_pre<false><<<dim3(8, 8), 256, PP_SMEM>>>(ptsh, ptsl, wth + 3 * WSZ, wtl + 3 * WSZ,
                                                  buq, qp, nullptr, nullptr);
    proj_pre<false><<<dim3(8, 8), 256, PP_SMEM>>>(ptsh, ptsl, wth + 4 * WSZ, wtl + 4 * WSZ,
                                                  buk, kp, nullptr, nullptr);

    // V^T per head, then split
    transpose_v<<<dim3(S_ / 32, DEPTH / 32, B_ * NUM_HEADS), tblk>>>(vc, vtf);
    split2<<<(N4_ACT + 255) / 256, 256>>>(vtf, vth, vtl, N4_ACT);

    // pos scores (theta patches fused)
    pos_mma<<<dim3(8, 8, NUM_HEADS), 256>>>(qp, kp, tcc, tco, toc, pos);

    // fused scores + softmax + AV
    flash_attn<<<dim3(8, 64), 256, FLASH_SMEM>>>(qch, qcl, kch, kcl, vth, vtl, pos, cxh, cxl);

    // output projection
    proj_pre<false><<<dim3(8, 32), 256, PP_SMEM>>>(cxh, cxl, wth + 5 * WSZ, wtl + 5 * WSZ,
                                                   bo, out, nullptr, nullptr);
}

// round 15
// speedup vs baseline: 1.3096x; 1.3096x over previous
#include <cuda_runtime.h>
#include <cuda_bf16.h>
#include <math.h>
#include <stdint.h>

#define D_MODEL 1024
#define NUM_HEADS 16
#define DEPTH 64
#define B_ 4
#define S_ 1024

// ---------------- scratch (static device globals; no allocation) -------------
__device__ float g_qc[(size_t)B_ * S_ * D_MODEL];            // 16 MB
__device__ float g_kc[(size_t)B_ * S_ * D_MODEL];            // 16 MB
__device__ float g_vc[(size_t)B_ * S_ * D_MODEL];            // 16 MB
__device__ float g_qp[(size_t)S_ * D_MODEL];                 // 4 MB
__device__ float g_kp[(size_t)S_ * D_MODEL];                 // 4 MB
__device__ float g_pos[(size_t)NUM_HEADS * S_ * S_];         // 64 MB
__device__ float g_ctx[(size_t)B_ * S_ * D_MODEL];           // 16 MB
__device__ float g_vt[(size_t)B_ * NUM_HEADS * DEPTH * S_];  // 16 MB (V^T per head)

// ============================================================================
// mma.sync helpers
// ============================================================================
__device__ __forceinline__ uint32_t smem_u32(const void* p) {
    uint32_t a;
    asm("{ .reg .u64 t; cvta.to.shared.u64 t, %1; cvt.u32.u64 %0, t; }" : "=r"(a) : "l"(p));
    return a;
}

__device__ __forceinline__ void ldsm4(uint32_t& r0, uint32_t& r1, uint32_t& r2,
                                      uint32_t& r3, uint32_t addr) {
    asm volatile("ldmatrix.sync.aligned.m8n8.x4.shared.b16 {%0,%1,%2,%3}, [%4];"
                 : "=r"(r0), "=r"(r1), "=r"(r2), "=r"(r3) : "r"(addr));
}

__device__ __forceinline__ void ldsm4t(uint32_t& r0, uint32_t& r1, uint32_t& r2,
                                       uint32_t& r3, uint32_t addr) {
    asm volatile("ldmatrix.sync.aligned.m8n8.x4.trans.shared.b16 {%0,%1,%2,%3}, [%4];"
                 : "=r"(r0), "=r"(r1), "=r"(r2), "=r"(r3) : "r"(addr));
}

__device__ __forceinline__ void mma16816(float* c, const uint32_t* a, const uint32_t* b) {
    asm volatile("mma.sync.aligned.m16n8k16.row.col.f32.bf16.bf16.f32 "
                 "{%0,%1,%2,%3}, {%4,%5,%6,%7}, {%8,%9}, {%0,%1,%2,%3};"
                 : "+f"(c[0]), "+f"(c[1]), "+f"(c[2]), "+f"(c[3])
                 : "r"(a[0]), "r"(a[1]), "r"(a[2]), "r"(a[3]), "r"(b[0]), "r"(b[1]));
}

__device__ __forceinline__ void split_pair(float x, float y, uint32_t& hi, uint32_t& lo) {
    __nv_bfloat162 h = __floats2bfloat162_rn(x, y);
    float hx = __bfloat162float(h.x);
    float hy = __bfloat162float(h.y);
    __nv_bfloat162 l = __floats2bfloat162_rn(x - hx, y - hy);
    hi = *reinterpret_cast<uint32_t*>(&h);
    lo = *reinterpret_cast<uint32_t*>(&l);
}

__device__ __forceinline__ void split_store(char* sH, char* sL, uint32_t off, float4 v) {
    uint32_t h0, l0, h1, l1;
    split_pair(v.x, v.y, h0, l0);
    split_pair(v.z, v.w, h1, l1);
    *(uint2*)(sH + off) = make_uint2(h0, h1);
    *(uint2*)(sL + off) = make_uint2(l0, l1);
}

// ============================================================================
// NN bf16x3 GEMM core: acc[128,128] += A[m0:,k] * W[k][n0:]
// A row-major (k contiguous), W row-major (n contiguous, read via ldmatrix.trans).
// BK=16, double-buffered SMEM (42 KB), one sync per K-iter. 256 threads.
// ============================================================================
__device__ __forceinline__ void gemm_nn(const float* __restrict__ A,
                                        const float* __restrict__ W,
                                        int m0, int n0, int kIters,
                                        float* __restrict__ acc)
{
    __shared__ __align__(16) __nv_bfloat16 sAh[2][128][24];
    __shared__ __align__(16) __nv_bfloat16 sAl[2][128][24];
    __shared__ __align__(16) __nv_bfloat16 sBh[2][16][136];
    __shared__ __align__(16) __nv_bfloat16 sBl[2][16][136];

    const int tid = threadIdx.x;
    const int lane = tid & 31, wid = tid >> 5;
    const int warp_n = wid & 3, warp_m = wid >> 2;

    const int rowA = tid >> 2, cA = tid & 3;       // A rows rowA, rowA+64
    const int rowB = tid >> 4, cB = (tid & 15) * 8; // W row k=rowB, cols cB..cB+7

    const float* Ap0 = A + (size_t)(m0 + rowA) * 1024 + cA * 4;
    const float* Ap1 = Ap0 + (size_t)64 * 1024;
    const float* Wp  = W + (size_t)rowB * 1024 + n0 + cB;

    const uint32_t stA = (uint32_t)rowA * 48u + (uint32_t)cA * 8u;
    const uint32_t stB = (uint32_t)rowB * 272u + (uint32_t)cB * 2u;

    char* aH = (char*)sAh; char* aL = (char*)sAl;
    char* bH = (char*)sBh; char* bL = (char*)sBl;
    const uint32_t aHb = smem_u32(sAh), aLb = smem_u32(sAl);
    const uint32_t bHb = smem_u32(sBh), bLb = smem_u32(sBl);
    const uint32_t ABUF = 128u * 48u;  // 6144 B
    const uint32_t BBUF = 16u * 272u;  // 4352 B

    // A frag (non-trans, row-major m x k)
    const uint32_t a_off =
        (uint32_t)((warp_m * 64 + (lane & 7) + ((lane >> 3) & 1) * 8) * 48 +
                   (lane >> 4) * 16);
    // B frag (trans, from row-major k x n): lanes 0-7:k0-7@n0, 8-15:k8-15@n0,
    // 16-23:k0-7@n0+8, 24-31:k8-15@n0+8
    const uint32_t b_off =
        (uint32_t)(((lane & 7) + ((lane >> 3) & 1) * 8) * 272 +
                   (warp_n * 32 + ((lane >> 4) & 1) * 8) * 2);

    float4 ra0 = *(const float4*)Ap0;
    float4 ra1 = *(const float4*)Ap1;
    float4 rb0 = *(const float4*)Wp;
    float4 rb1 = *(const float4*)(Wp + 4);

    split_store(aH, aL, stA, ra0);
    split_store(aH, aL, stA + 64u * 48u, ra1);
    split_store(bH, bL, stB, rb0);
    split_store(bH, bL, stB + 8u, rb1);
    __syncthreads();

    for (int it = 0; it < kIters; ++it) {
        const uint32_t buf = (uint32_t)(it & 1);
        const uint32_t aoff = buf * ABUF, boff = buf * BBUF;

        // prefetch next chunk (LDG latency hidden behind MMA below)
        if (it + 1 < kIters) {
            const int ko = (it + 1) * 16;
            ra0 = *(const float4*)(Ap0 + ko);
            ra1 = *(const float4*)(Ap1 + ko);
            rb0 = *(const float4*)(Wp + (size_t)ko * 1024);
            rb1 = *(const float4*)(Wp + (size_t)ko * 1024 + 4);
        }

        uint32_t ah[4][4], bh[4][2];
#pragma unroll
        for (int mt = 0; mt < 4; mt++)
            ldsm4(ah[mt][0], ah[mt][1], ah[mt][2], ah[mt][3],
                  aHb + aoff + a_off + (uint32_t)(mt * 16 * 48));
#pragma unroll
        for (int p = 0; p < 2; p++) {
            uint32_t t0, t1, t2, t3;
            ldsm4t(t0, t1, t2, t3, bHb + boff + b_off + (uint32_t)(p * 32));
            bh[2 * p][0] = t0; bh[2 * p][1] = t1;
            bh[2 * p + 1][0] = t2; bh[2 * p + 1][1] = t3;
        }
#pragma unroll
        for (int mt = 0; mt < 4; mt++)
#pragma unroll
            for (int nt = 0; nt < 4; nt++)
                mma16816(acc + (mt * 4 + nt) * 4, ah[mt], bh[nt]);

        uint32_t bl[4][2];
#pragma unroll
        for (int p = 0; p < 2; p++) {
            uint32_t t0, t1, t2, t3;
            ldsm4t(t0, t1, t2, t3, bLb + boff + b_off + (uint32_t)(p * 32));
            bl[2 * p][0] = t0; bl[2 * p][1] = t1;
            bl[2 * p + 1][0] = t2; bl[2 * p + 1][1] = t3;
        }
#pragma unroll
        for (int mt = 0; mt < 4; mt++)
#pragma unroll
            for (int nt = 0; nt < 4; nt++)
                mma16816(acc + (mt * 4 + nt) * 4, ah[mt], bl[nt]);

        uint32_t al[4][4];
#pragma unroll
        for (int mt = 0; mt < 4; mt++)
            ldsm4(al[mt][0], al[mt][1], al[mt][2], al[mt][3],
                  aLb + aoff + a_off + (uint32_t)(mt * 16 * 48));
#pragma unroll
        for (int mt = 0; mt < 4; mt++)
#pragma unroll
            for (int nt = 0; nt < 4; nt++)
                mma16816(acc + (mt * 4 + nt) * 4, al[mt], bh[nt]);

        // store next chunk into the other buffer (no conflict with readers of buf)
        if (it + 1 < kIters) {
            const uint32_t nb = (buf ^ 1u);
            split_store(aH, aL, nb * ABUF + stA, ra0);
            split_store(aH, aL, nb * ABUF + stA + 64u * 48u, ra1);
            split_store(bH, bL, nb * BBUF + stB, rb0);
            split_store(bH, bL, nb * BBUF + stB + 8u, rb1);
        }
        __syncthreads();
    }
}

__device__ __forceinline__ void epilogue_bias(const float* __restrict__ acc,
                                              const float* __restrict__ bias,
                                              float* __restrict__ out,
                                              int m0, int n0)
{
    const int lane = threadIdx.x & 31, wid = threadIdx.x >> 5;
    const int warp_n = wid & 3, warp_m = wid >> 2;
    const int rbase = m0 + warp_m * 64 + (lane >> 2);
    const int cbase = n0 + warp_n * 32 + (lane & 3) * 2;
#pragma unroll
    for (int mt = 0; mt < 4; mt++)
#pragma unroll
        for (int nt = 0; nt < 4; nt++) {
            const float* a = acc + (mt * 4 + nt) * 4;
            const int r = rbase + mt * 16;
            const int c = cbase + nt * 8;
            float2 b2 = *(const float2*)(bias + c);
            *(float2*)(out + (size_t)r * 1024 + c) = make_float2(a[0] + b2.x, a[1] + b2.y);
            *(float2*)(out + (size_t)(r + 8) * 1024 + c) = make_float2(a[2] + b2.x, a[3] + b2.y);
        }
}

// ============================================================================
// Merged Q/K/V projection: grid (24, 32); seg = blockIdx.x/8 picks q/k/v.
// ============================================================================
__global__ __launch_bounds__(256, 1)
void proj_qkv(const float* __restrict__ q, const float* __restrict__ k,
              const float* __restrict__ v,
              const float* __restrict__ Wq, const float* __restrict__ Wk,
              const float* __restrict__ Wv,
              const float* __restrict__ bq, const float* __restrict__ bk,
              const float* __restrict__ bv,
              float* __restrict__ qc, float* __restrict__ kc, float* __restrict__ vc)
{
    const int seg = blockIdx.x >> 3;
    const int n0 = (blockIdx.x & 7) * 128;
    const int m0 = blockIdx.y * 128;
    const float* A = (seg == 0) ? q : (seg == 1) ? k : v;
    const float* W = (seg == 0) ? Wq : (seg == 1) ? Wk : Wv;
    const float* bias = (seg == 0) ? bq : (seg == 1) ? bk : bv;
    float* out = (seg == 0) ? qc : (seg == 1) ? kc : vc;

    float acc[64];
#pragma unroll
    for (int i = 0; i < 64; i++) acc[i] = 0.0f;
    gemm_nn(A, W, m0, n0, 64, acc);
    epilogue_bias(acc, bias, out, m0, n0);
}

// Merged positional projections: grid (16, 8); seg picks Uq/Uk.
__global__ __launch_bounds__(256, 1)
void proj_u(const float* __restrict__ pt,
            const float* __restrict__ Uq, const float* __restrict__ Uk,
            const float* __restrict__ buq, const float* __restrict__ buk,
            float* __restrict__ qp, float* __restrict__ kp)
{
    const int seg = blockIdx.x >> 3;
    const int n0 = (blockIdx.x & 7) * 128;
    const int m0 = blockIdx.y * 128;
    const float* W = (seg == 0) ? Uq : Uk;
    const float* bias = (seg == 0) ? buq : buk;
    float* out = (seg == 0) ? qp : kp;

    float acc[64];
#pragma unroll
    for (int i = 0; i < 64; i++) acc[i] = 0.0f;
    gemm_nn(pt, W, m0, n0, 64, acc);
    epilogue_bias(acc, bias, out, m0, n0);
}

// Output projection: grid (8, 32)
__global__ __launch_bounds__(256, 1)
void proj_o(const float* __restrict__ ctx, const float* __restrict__ Wo,
            const float* __restrict__ bo, float* __restrict__ out)
{
    const int n0 = blockIdx.x * 128;
    const int m0 = blockIdx.y * 128;
    float acc[64];
#pragma unroll
    for (int i = 0; i < 64; i++) acc[i] = 0.0f;
    gemm_nn(ctx, Wo, m0, n0, 64, acc);
    epilogue_bias(acc, bo, out, m0, n0);
}

// ============================================================================
// NT bf16x3 core (fp32 in) — for pos_mma (K=64)  [R13, unchanged]
// ============================================================================
template <int BN>
__device__ __forceinline__ void gemm_bf16x3(
    const float* __restrict__ A, int lda, int m0,
    const float* __restrict__ Bt, int ldb, int n0,
    int kIters, float* __restrict__ acc)
{
    constexpr int NWN = BN / 32;
    constexpr int NWM = 8 / NWN;
    constexpr int WROWS = 128 / NWM;
    constexpr int MT = WROWS / 16;

    __shared__ __align__(16) __nv_bfloat16 sAh[128][24];
    __shared__ __align__(16) __nv_bfloat16 sAl[128][24];
    __shared__ __align__(16) __nv_bfloat16 sBh[BN][24];
    __shared__ __align__(16) __nv_bfloat16 sBl[BN][24];

    const int tid = threadIdx.x;
    const int lane = tid & 31;
    const int wid = tid >> 5;
    const int warp_n = wid % NWN;
    const int warp_m = wid / NWN;

    const int row0 = tid >> 2;
    const int c0 = tid & 3;

    const float* ApA = A + (size_t)(m0 + row0) * lda + c0 * 4;
    const float* ApB = ApA + (size_t)64 * lda;
    const float* BpA = Bt + (size_t)(n0 + row0) * ldb + c0 * 4;
    const float* BpB = BpA + (size_t)64 * ldb;

    const uint32_t stA = (uint32_t)row0 * 48u + (uint32_t)c0 * 8u;
    const uint32_t stB = stA + 64u * 48u;

    const uint32_t baseAh = smem_u32(sAh);
    const uint32_t baseAl = smem_u32(sAl);
    const uint32_t baseBh = smem_u32(sBh);
    const uint32_t baseBl = smem_u32(sBl);

    const uint32_t a_off =
        (uint32_t)((warp_m * WROWS + (lane & 7) + ((lane >> 3) & 1) * 8) * 48 +
                   (lane >> 4) * 16);
    const uint32_t b_off =
        (uint32_t)((warp_n * 32 + (lane & 7) + ((lane >> 4) & 1) * 8) * 48 +
                   ((lane >> 3) & 1) * 16);

    float4 ra0 = *(const float4*)ApA;
    float4 ra1 = *(const float4*)ApB;
    float4 rb0 = *(const float4*)BpA;
    float4 rb1 = make_float4(0.f, 0.f, 0.f, 0.f);
    if (BN == 128) rb1 = *(const float4*)BpB;

    for (int it = 0; it < kIters; ++it) {
        __syncthreads();
        split_store((char*)sAh, (char*)sAl, stA, ra0);
        split_store((char*)sAh, (char*)sAl, stB, ra1);
        split_store((char*)sBh, (char*)sBl, stA, rb0);
        if (BN == 128) split_store((char*)sBh, (char*)sBl, stB, rb1);
        __syncthreads();

        if (it + 1 < kIters) {
            const int ko = (it + 1) * 16;
            ra0 = *(const float4*)(ApA + ko);
            ra1 = *(const float4*)(ApB + ko);
            rb0 = *(const float4*)(BpA + ko);
            if (BN == 128) rb1 = *(const float4*)(BpB + ko);
        }

        uint32_t ah[MT][4], bh[4][2];
#pragma unroll
        for (int mt = 0; mt < MT; mt++)
            ldsm4(ah[mt][0], ah[mt][1], ah[mt][2], ah[mt][3],
                  baseAh + a_off + (uint32_t)(mt * 16 * 48));
#pragma unroll
        for (int p = 0; p < 2; p++) {
            uint32_t t0, t1, t2, t3;
            ldsm4(t0, t1, t2, t3, baseBh + b_off + (uint32_t)(p * 16 * 48));
            bh[2 * p][0] = t0; bh[2 * p][1] = t1;
            bh[2 * p + 1][0] = t2; bh[2 * p + 1][1] = t3;
        }
#pragma unroll
        for (int mt = 0; mt < MT; mt++)
#pragma unroll
            for (int nt = 0; nt < 4; nt++)
                mma16816(acc + (mt * 4 + nt) * 4, ah[mt], bh[nt]);

        uint32_t bl[4][2];
#pragma unroll
        for (int p = 0; p < 2; p++) {
            uint32_t t0, t1, t2, t3;
            ldsm4(t0, t1, t2, t3, baseBl + b_off + (uint32_t)(p * 16 * 48));
            bl[2 * p][0] = t0; bl[2 * p][1] = t1;
            bl[2 * p + 1][0] = t2; bl[2 * p + 1][1] = t3;
        }
#pragma unroll
        for (int mt = 0; mt < MT; mt++)
#pragma unroll
            for (int nt = 0; nt < 4; nt++)
                mma16816(acc + (mt * 4 + nt) * 4, ah[mt], bl[nt]);

        uint32_t al[MT][4];
#pragma unroll
        for (int mt = 0; mt < MT; mt++)
            ldsm4(al[mt][0], al[mt][1], al[mt][2], al[mt][3],
                  baseAl + a_off + (uint32_t)(mt * 16 * 48));
#pragma unroll
        for (int mt = 0; mt < MT; mt++)
#pragma unroll
            for (int nt = 0; nt < 4; nt++)
                mma16816(acc + (mt * 4 + nt) * 4, al[mt], bh[nt]);
    }
}

// ============================================================================
// pos scores: pos[h] = q_p @ k_p^T with theta patches; K=64  [R13, unchanged]
// ============================================================================
__global__ __launch_bounds__(256, 1)
void pos_mma(const float* __restrict__ qp, const float* __restrict__ kp,
             const float* __restrict__ tcc, const float* __restrict__ tco,
             const float* __restrict__ toc, float* __restrict__ pos)
{
    const int h = blockIdx.z;
    float acc[64];
#pragma unroll
    for (int i = 0; i < 64; i++) acc[i] = 0.0f;
    const int m0 = blockIdx.y * 128, n0 = blockIdx.x * 128;
    gemm_bf16x3<128>(qp + h * DEPTH, 1024, m0, kp + h * DEPTH, 1024, n0, 4, acc);

    const float thcc = tcc[h], thco = tco[h], thoc = toc[h];
    float* O = pos + (size_t)h * S_ * S_;

    const int lane = threadIdx.x & 31, wid = threadIdx.x >> 5;
    const int warp_n = wid & 3, warp_m = wid >> 2;
    const int rbase = m0 + warp_m * 64 + (lane >> 2);
    const int cbase = n0 + warp_n * 32 + (lane & 3) * 2;
#pragma unroll
    for (int mt = 0; mt < 4; mt++)
#pragma unroll
        for (int nt = 0; nt < 4; nt++) {
            const float* a = acc + (mt * 4 + nt) * 4;
            const int r = rbase + mt * 16;
            const int c = cbase + nt * 8;
            float v0 = a[0], v1 = a[1], v2 = a[2], v3 = a[3];
            if (r == 0) { v0 = (c == 0) ? thcc : thco; v1 = thco; }
            else if (c == 0) v0 = thoc;
            if (c == 0) v2 = thoc;
            *(float2*)(O + (size_t)r * 1024 + c) = make_float2(v0, v1);
            *(float2*)(O + (size_t)(r + 8) * 1024 + c) = make_float2(v2, v3);
        }
}

// ============================================================================
// Fused flash attention  [R13, unchanged]
// ============================================================================
#define QK_STRIDE 144
#define VT_STRIDE 272
#define QH_OFF 0
#define QL_OFF 18432
#define KH_OFF 36864
#define KL_OFF 55296
#define VH_OFF 73728
#define VL_OFF 91136
#define RS_OFF 108544
#define FLASH_SMEM 110592

__global__ __launch_bounds__(256, 1)
void flash_attn(const float* __restrict__ qc, const float* __restrict__ kc,
                const float* __restrict__ vt, const float* __restrict__ pos,
                float* __restrict__ ctx)
{
    extern __shared__ char sm[];
    char* qh = sm + QH_OFF;  char* ql = sm + QL_OFF;
    char* kh = sm + KH_OFF;  char* kl = sm + KL_OFF;
    char* vh = sm + VH_OFF;  char* vl = sm + VL_OFF;
    float* rsum_sm = (float*)(sm + RS_OFF);

    const int bh = blockIdx.y;
    const int b = bh >> 4, h = bh & 15;
    const int m0 = blockIdx.x * 128;

    const int tid = threadIdx.x;
    const int lane = tid & 31;
    const int wid = tid >> 5;
    const int warp_m = wid >> 2;
    const int warp_n = wid & 3;

    const float* Qb = qc + ((size_t)b * S_ + m0) * D_MODEL + h * DEPTH;
    const float* Kb = kc + (size_t)b * S_ * D_MODEL + h * DEPTH;
    const float* Vb = vt + (size_t)bh * DEPTH * S_;
    const float* Pb = pos + (size_t)h * S_ * S_;

    const uint32_t qh_b = smem_u32(qh), ql_b = smem_u32(ql);
    const uint32_t kh_b = smem_u32(kh), kl_b = smem_u32(kl);
    const uint32_t vh_b = smem_u32(vh), vl_b = smem_u32(vl);

    const int row0 = tid >> 2;
    const int c0 = tid & 3;

#pragma unroll
    for (int kcix = 0; kcix < 4; kcix++) {
        float4 v0 = *(const float4*)(Qb + (size_t)row0 * 1024 + kcix * 16 + c0 * 4);
        float4 v1 = *(const float4*)(Qb + (size_t)(row0 + 64) * 1024 + kcix * 16 + c0 * 4);
        split_store(qh, ql, (uint32_t)row0 * QK_STRIDE + kcix * 32 + c0 * 8, v0);
        split_store(qh, ql, (uint32_t)(row0 + 64) * QK_STRIDE + kcix * 32 + c0 * 8, v1);
    }

    const uint32_t a_off =
        (uint32_t)((warp_m * 64 + (lane & 7) + ((lane >> 3) & 1) * 8) * QK_STRIDE +
                   (lane >> 4) * 16);
    const uint32_t b_off =
        (uint32_t)((warp_n * 32 + (lane & 7) + ((lane >> 4) & 1) * 8) * QK_STRIDE +
                   ((lane >> 3) & 1) * 16);
    const uint32_t bv_off =
        (uint32_t)((warp_n * 16 + (lane & 7) + ((lane >> 4) & 1) * 8) * VT_STRIDE +
                   ((lane >> 3) & 1) * 16);

    const int rbase = warp_m * 64 + (lane >> 2);
    const int cbase = warp_n * 32 + (lane & 3) * 2;
    const int khalf = warp_n >> 1;
    const int clocal = (warp_n & 1) * 32 + (lane & 3) * 2;

    float oacc[32];
#pragma unroll
    for (int i = 0; i < 32; i++) oacc[i] = 0.0f;
    float rs[8];
#pragma unroll
    for (int i = 0; i < 8; i++) rs[i] = 0.0f;

    for (int j = 0; j < 8; ++j) {
        __syncthreads();

#pragma unroll
        for (int kcix = 0; kcix < 4; kcix++) {
            float4 v0 = *(const float4*)(Kb + (size_t)(j * 128 + row0) * 1024 + kcix * 16 + c0 * 4);
            float4 v1 = *(const float4*)(Kb + (size_t)(j * 128 + row0 + 64) * 1024 + kcix * 16 + c0 * 4);
            split_store(kh, kl, (uint32_t)row0 * QK_STRIDE + kcix * 32 + c0 * 8, v0);
            split_store(kh, kl, (uint32_t)(row0 + 64) * QK_STRIDE + kcix * 32 + c0 * 8, v1);
        }
#pragma unroll
        for (int cc = 0; cc < 8; cc++) {
            float4 v0 = *(const float4*)(Vb + (size_t)row0 * S_ + j * 128 + cc * 16 + c0 * 4);
            split_store(vh, vl, (uint32_t)row0 * VT_STRIDE + cc * 32 + c0 * 8, v0);
        }
        __syncthreads();

        float sacc[64];
#pragma unroll
        for (int i = 0; i < 64; i++) sacc[i] = 0.0f;

        for (int ki = 0; ki < 4; ++ki) {
            const uint32_t ko = (uint32_t)(ki * 32);
            uint32_t ah[4][4], bhf[4][2];
#pragma unroll
            for (int mt = 0; mt < 4; mt++)
                ldsm4(ah[mt][0], ah[mt][1], ah[mt][2], ah[mt][3],
                      qh_b + a_off + (uint32_t)(mt * 16 * QK_STRIDE) + ko);
#pragma unroll
            for (int p = 0; p < 2; p++) {
                uint32_t t0, t1, t2, t3;
                ldsm4(t0, t1, t2, t3, kh_b + b_off + (uint32_t)(p * 16 * QK_STRIDE) + ko);
                bhf[2 * p][0] = t0; bhf[2 * p][1] = t1;
                bhf[2 * p + 1][0] = t2; bhf[2 * p + 1][1] = t3;
            }
#pragma unroll
            for (int mt = 0; mt < 4; mt++)
#pragma unroll
                for (int nt = 0; nt < 4; nt++)
                    mma16816(sacc + (mt * 4 + nt) * 4, ah[mt], bhf[nt]);

            uint32_t blf[4][2];
#pragma unroll
            for (int p = 0; p < 2; p++) {
                uint32_t t0, t1, t2, t3;
                ldsm4(t0, t1, t2, t3, kl_b + b_off + (uint32_t)(p * 16 * QK_STRIDE) + ko);
                blf[2 * p][0] = t0; blf[2 * p][1] = t1;
                blf[2 * p + 1][0] = t2; blf[2 * p + 1][1] = t3;
            }
#pragma unroll
            for (int mt = 0; mt < 4; mt++)
#pragma unroll
                for (int nt = 0; nt < 4; nt++)
                    mma16816(sacc + (mt * 4 + nt) * 4, ah[mt], blf[nt]);

            uint32_t al[4][4];
#pragma unroll
            for (int mt = 0; mt < 4; mt++)
                ldsm4(al[mt][0], al[mt][1], al[mt][2], al[mt][3],
                      ql_b + a_off + (uint32_t)(mt * 16 * QK_STRIDE) + ko);
#pragma unroll
            for (int mt = 0; mt < 4; mt++)
#pragma unroll
                for (int nt = 0; nt < 4; nt++)
                    mma16816(sacc + (mt * 4 + nt) * 4, al[mt], bhf[nt]);
        }

#pragma unroll
        for (int mt = 0; mt < 4; mt++) {
            const int r = rbase + mt * 16;
#pragma unroll
            for (int nt = 0; nt < 4; nt++) {
                float* a = sacc + (mt * 4 + nt) * 4;
                const int cg = j * 128 + cbase + nt * 8;
                float2 p0 = *(const float2*)(Pb + (size_t)(m0 + r) * 1024 + cg);
                float2 p1 = *(const float2*)(Pb + (size_t)(m0 + r + 8) * 1024 + cg);
                a[0] = __expf((a[0] + p0.x) * 0.125f);
                a[1] = __expf((a[1] + p0.y) * 0.125f);
                a[2] = __expf((a[2] + p1.x) * 0.125f);
                a[3] = __expf((a[3] + p1.y) * 0.125f);
                rs[mt * 2 + 0] += a[0] + a[1];
                rs[mt * 2 + 1] += a[2] + a[3];
            }
        }

#pragma unroll
        for (int half = 0; half < 2; ++half) {
            __syncthreads();
            if (khalf == half) {
#pragma unroll
                for (int mt = 0; mt < 4; mt++) {
                    const int r = rbase + mt * 16;
#pragma unroll
                    for (int nt = 0; nt < 4; nt++) {
                        float* a = sacc + (mt * 4 + nt) * 4;
                        const uint32_t co = (uint32_t)(clocal + nt * 8) * 2u;
                        uint32_t hi, lo;
                        split_pair(a[0], a[1], hi, lo);
                        *(uint32_t*)(kh + (uint32_t)r * QK_STRIDE + co) = hi;
                        *(uint32_t*)(kl + (uint32_t)r * QK_STRIDE + co) = lo;
                        split_pair(a[2], a[3], hi, lo);
                        *(uint32_t*)(kh + (uint32_t)(r + 8) * QK_STRIDE + co) = hi;
                        *(uint32_t*)(kl + (uint32_t)(r + 8) * QK_STRIDE + co) = lo;
                    }
                }
            }
            __syncthreads();

            const uint32_t vcol = (uint32_t)(half * 128);
            for (int ki = 0; ki < 4; ++ki) {
                const uint32_t ko = (uint32_t)(ki * 32);
                uint32_t pa[4][4], vbh[2][2], vbl[2][2];
#pragma unroll
                for (int mt = 0; mt < 4; mt++)
                    ldsm4(pa[mt][0], pa[mt][1], pa[mt][2], pa[mt][3],
                          kh_b + a_off + (uint32_t)(mt * 16 * QK_STRIDE) + ko);
                {
                    uint32_t t0, t1, t2, t3;
                    ldsm4(t0, t1, t2, t3, vh_b + bv_off + vcol + ko);
                    vbh[0][0] = t0; vbh[0][1] = t1; vbh[1][0] = t2; vbh[1][1] = t3;
                    ldsm4(t0, t1, t2, t3, vl_b + bv_off + vcol + ko);
                    vbl[0][0] = t0; vbl[0][1] = t1; vbl[1][0] = t2; vbl[1][1] = t3;
                }
#pragma unroll
                for (int mt = 0; mt < 4; mt++)
#pragma unroll
                    for (int nt = 0; nt < 2; nt++) {
                        mma16816(oacc + (mt * 2 + nt) * 4, pa[mt], vbh[nt]);
                        mma16816(oacc + (mt * 2 + nt) * 4, pa[mt], vbl[nt]);
                    }
                uint32_t pl[4][4];
#pragma unroll
                for (int mt = 0; mt < 4; mt++)
                    ldsm4(pl[mt][0], pl[mt][1], pl[mt][2], pl[mt][3],
                          kl_b + a_off + (uint32_t)(mt * 16 * QK_STRIDE) + ko);
#pragma unroll
                for (int mt = 0; mt < 4; mt++)
#pragma unroll
                    for (int nt = 0; nt < 2; nt++)
                        mma16816(oacc + (mt * 2 + nt) * 4, pl[mt], vbh[nt]);
            }
        }
    }

#pragma unroll
    for (int i = 0; i < 8; i++) {
        rs[i] += __shfl_xor_sync(0xffffffffu, rs[i], 1);
        rs[i] += __shfl_xor_sync(0xffffffffu, rs[i], 2);
    }
    if ((lane & 3) == 0) {
#pragma unroll
        for (int mt = 0; mt < 4; mt++) {
            rsum_sm[warp_n * 128 + rbase + mt * 16] = rs[mt * 2 + 0];
            rsum_sm[warp_n * 128 + rbase + mt * 16 + 8] = rs[mt * 2 + 1];
        }
    }
    __syncthreads();

    float* Ob = ctx + ((size_t)b * S_ + m0) * D_MODEL + h * DEPTH;
    const int cob = warp_n * 16 + (lane & 3) * 2;
#pragma unroll
    for (int mt = 0; mt < 4; mt++) {
        const int r = rbase + mt * 16;
        const float inv0 = 1.0f / (rsum_sm[r] + rsum_sm[128 + r] +
                                   rsum_sm[256 + r] + rsum_sm[384 + r]);
        const float inv1 = 1.0f / (rsum_sm[r + 8] + rsum_sm[128 + r + 8] +
                                   rsum_sm[256 + r + 8] + rsum_sm[384 + r + 8]);
#pragma unroll
        for (int nt = 0; nt < 2; nt++) {
            const float* a = oacc + (mt * 2 + nt) * 4;
            const int c = cob + nt * 8;
            *(float2*)(Ob + (size_t)r * 1024 + c) = make_float2(a[0] * inv0, a[1] * inv0);
            *(float2*)(Ob + (size_t)(r + 8) * 1024 + c) = make_float2(a[2] * inv1, a[3] * inv1);
        }
    }
}

// ============================================================================
// V transpose (fp32)  [R13, unchanged]
// ============================================================================
__global__ __launch_bounds__(256)
void transpose_v(const float* __restrict__ vc, float* __restrict__ vt) {
    __shared__ float t[32][33];
    const int bh = blockIdx.z;
    const int b = bh >> 4, h = bh & 15;
    const int s0 = blockIdx.x * 32, d0 = blockIdx.y * 32;
    const int txx = threadIdx.x, tyy = threadIdx.y;
#pragma unroll
    for (int i = tyy; i < 32; i += 8)
        t[i][txx] = vc[((size_t)b * S_ + s0 + i) * D_MODEL + h * DEPTH + d0 + txx];
    __syncthreads();
#pragma unroll
    for (int i = tyy; i < 32; i += 8)
        vt[(size_t)bh * DEPTH * S_ + (size_t)(d0 + i) * S_ + s0 + txx] = t[txx][i];
}

// ============================================================================
// kernel_launch
// ============================================================================
extern "C" void kernel_launch(void* const* d_in, const int* in_sizes, int n_in,
                              void* d_out, int out_size)
{
    (void)in_sizes; (void)n_in; (void)out_size;

    const float* q   = (const float*)d_in[0];
    const float* k   = (const float*)d_in[1];
    const float* v   = (const float*)d_in[2];
    const float* Wq  = (const float*)d_in[3];
    const float* bq  = (const float*)d_in[4];
    const float* Wk  = (const float*)d_in[5];
    const float* bk  = (const float*)d_in[6];
    const float* Wv  = (const float*)d_in[7];
    const float* bv  = (const float*)d_in[8];
    const float* Uq  = (const float*)d_in[9];
    const float* buq = (const float*)d_in[10];
    const float* Uk  = (const float*)d_in[11];
    const float* buk = (const float*)d_in[12];
    const float* pt  = (const float*)d_in[13];
    const float* tcc = (const float*)d_in[14];
    const float* tco = (const float*)d_in[15];
    const float* toc = (const float*)d_in[16];
    const float* Wo  = (const float*)d_in[17];
    const float* bo  = (const float*)d_in[18];
    float* out = (float*)d_out;

    float *qc, *kc, *vc, *qp, *kp, *pos, *ctx, *vt;
    cudaGetSymbolAddress((void**)&qc, g_qc);
    cudaGetSymbolAddress((void**)&kc, g_kc);
    cudaGetSymbolAddress((void**)&vc, g_vc);
    cudaGetSymbolAddress((void**)&qp, g_qp);
    cudaGetSymbolAddress((void**)&kp, g_kp);
    cudaGetSymbolAddress((void**)&pos, g_pos);
    cudaGetSymbolAddress((void**)&ctx, g_ctx);
    cudaGetSymbolAddress((void**)&vt, g_vt);

    cudaFuncSetAttribute(flash_attn,
                         cudaFuncAttributeMaxDynamicSharedMemorySize, FLASH_SMEM);

    // Q/K/V projections in one launch (no weight transposes needed)
    proj_qkv<<<dim3(24, 32), 256>>>(q, k, v, Wq, Wk, Wv, bq, bk, bv, qc, kc, vc);

    // positional projections in one launch
    proj_u<<<dim3(16, 8), 256>>>(pt, Uq, Uk, buq, buk, qp, kp);

    // V^T per head
    transpose_v<<<dim3(S_ / 32, DEPTH / 32, B_ * NUM_HEADS), dim3(32, 8)>>>(vc, vt);

    // pos scores (theta patches fused)
    pos_mma<<<dim3(8, 8, NUM_HEADS), 256>>>(qp, kp, tcc, tco, toc, pos);

    // fused scores + softmax + AV
    flash_attn<<<dim3(8, 64), 256, FLASH_SMEM>>>(qc, kc, vt, pos, ctx);

    // output projection
    proj_o<<<dim3(8, 32), 256>>>(ctx, Wo, bo, out);
}

// round 16
// speedup vs baseline: 1.4240x; 1.0873x over previous
#include <cuda_runtime.h>
#include <cuda_bf16.h>
#include <math.h>
#include <stdint.h>

#define D_MODEL 1024
#define NUM_HEADS 16
#define DEPTH 64
#define B_ 4
#define S_ 1024

// ---------------- scratch (static device globals; no allocation) -------------
__device__ float g_qc[(size_t)B_ * S_ * D_MODEL];            // 16 MB
__device__ float g_kc[(size_t)B_ * S_ * D_MODEL];            // 16 MB
__device__ float g_vc[(size_t)B_ * S_ * D_MODEL];            // 16 MB
__device__ float g_qp[(size_t)S_ * D_MODEL];                 // 4 MB
__device__ float g_kp[(size_t)S_ * D_MODEL];                 // 4 MB
__device__ float g_pos[(size_t)NUM_HEADS * S_ * S_];         // 64 MB
__device__ float g_ctx[(size_t)B_ * S_ * D_MODEL];           // 16 MB
__device__ float g_vt[(size_t)B_ * NUM_HEADS * DEPTH * S_];  // 16 MB (V^T per head)

// ============================================================================
// mma.sync helpers
// ============================================================================
__device__ __forceinline__ uint32_t smem_u32(const void* p) {
    uint32_t a;
    asm("{ .reg .u64 t; cvta.to.shared.u64 t, %1; cvt.u32.u64 %0, t; }" : "=r"(a) : "l"(p));
    return a;
}

__device__ __forceinline__ void ldsm4(uint32_t& r0, uint32_t& r1, uint32_t& r2,
                                      uint32_t& r3, uint32_t addr) {
    asm volatile("ldmatrix.sync.aligned.m8n8.x4.shared.b16 {%0,%1,%2,%3}, [%4];"
                 : "=r"(r0), "=r"(r1), "=r"(r2), "=r"(r3) : "r"(addr));
}

__device__ __forceinline__ void ldsm4t(uint32_t& r0, uint32_t& r1, uint32_t& r2,
                                       uint32_t& r3, uint32_t addr) {
    asm volatile("ldmatrix.sync.aligned.m8n8.x4.trans.shared.b16 {%0,%1,%2,%3}, [%4];"
                 : "=r"(r0), "=r"(r1), "=r"(r2), "=r"(r3) : "r"(addr));
}

__device__ __forceinline__ void mma16816(float* c, const uint32_t* a, const uint32_t* b) {
    asm volatile("mma.sync.aligned.m16n8k16.row.col.f32.bf16.bf16.f32 "
                 "{%0,%1,%2,%3}, {%4,%5,%6,%7}, {%8,%9}, {%0,%1,%2,%3};"
                 : "+f"(c[0]), "+f"(c[1]), "+f"(c[2]), "+f"(c[3])
                 : "r"(a[0]), "r"(a[1]), "r"(a[2]), "r"(a[3]), "r"(b[0]), "r"(b[1]));
}

__device__ __forceinline__ void split_pair(float x, float y, uint32_t& hi, uint32_t& lo) {
    __nv_bfloat162 h = __floats2bfloat162_rn(x, y);
    float hx = __bfloat162float(h.x);
    float hy = __bfloat162float(h.y);
    __nv_bfloat162 l = __floats2bfloat162_rn(x - hx, y - hy);
    hi = *reinterpret_cast<uint32_t*>(&h);
    lo = *reinterpret_cast<uint32_t*>(&l);
}

__device__ __forceinline__ void split_store(char* sH, char* sL, uint32_t off, float4 v) {
    uint32_t h0, l0, h1, l1;
    split_pair(v.x, v.y, h0, l0);
    split_pair(v.z, v.w, h1, l1);
    *(uint2*)(sH + off) = make_uint2(h0, h1);
    *(uint2*)(sL + off) = make_uint2(l0, l1);
}

// ============================================================================
// NN bf16x3 GEMM core, 512 threads (16 warps = 4 warps/SMSP):
// acc[128,128] += A[m0:,k] * W[k][n0:]
// A row-major (k contiguous), W row-major (n contiguous, ldmatrix.trans).
// Warp grid 4(m) x 4(n), warp tile 32x32. BK=16, double-buffered, 1 sync/iter.
// ============================================================================
__device__ __forceinline__ void gemm_nn512(const float* __restrict__ A,
                                           const float* __restrict__ W,
                                           int m0, int n0, int kIters,
                                           float* __restrict__ acc /*32*/)
{
    __shared__ __align__(16) __nv_bfloat16 sAh[2][128][24];
    __shared__ __align__(16) __nv_bfloat16 sAl[2][128][24];
    __shared__ __align__(16) __nv_bfloat16 sBh[2][16][136];
    __shared__ __align__(16) __nv_bfloat16 sBl[2][16][136];

    const int tid = threadIdx.x;
    const int lane = tid & 31, wid = tid >> 5;
    const int warp_n = wid & 3, warp_m = wid >> 2;   // 4 x 4 warps

    const int rowA = tid >> 2, cA = tid & 3;          // 128 rows x 4 quarters
    const int rowB = tid >> 5, cB = (tid & 31) * 4;   // 16 rows x 32 quarters

    const float* Ap = A + (size_t)(m0 + rowA) * 1024 + cA * 4;
    const float* Wp = W + (size_t)rowB * 1024 + n0 + cB;

    const uint32_t stA = (uint32_t)rowA * 48u + (uint32_t)cA * 8u;
    const uint32_t stB = (uint32_t)rowB * 272u + (uint32_t)cB * 2u;

    char* aH = (char*)sAh; char* aL = (char*)sAl;
    char* bH = (char*)sBh; char* bL = (char*)sBl;
    const uint32_t aHb = smem_u32(sAh), aLb = smem_u32(sAl);
    const uint32_t bHb = smem_u32(sBh), bLb = smem_u32(sBl);
    const uint32_t ABUF = 128u * 48u;   // 6144 B
    const uint32_t BBUF = 16u * 272u;   // 4352 B

    // A frag (non-trans): warp rows warp_m*32 .. +31, MT=2 tiles of 16
    const uint32_t a_off =
        (uint32_t)((warp_m * 32 + (lane & 7) + ((lane >> 3) & 1) * 8) * 48 +
                   (lane >> 4) * 16);
    // B frag (trans, row-major k x n)
    const uint32_t b_off =
        (uint32_t)(((lane & 7) + ((lane >> 3) & 1) * 8) * 272 +
                   (warp_n * 32 + ((lane >> 4) & 1) * 8) * 2);

    float4 ra = *(const float4*)Ap;
    float4 rb = *(const float4*)Wp;

    split_store(aH, aL, stA, ra);
    split_store(bH, bL, stB, rb);
    __syncthreads();

    for (int it = 0; it < kIters; ++it) {
        const uint32_t buf = (uint32_t)(it & 1);
        const uint32_t aoff = buf * ABUF, boff = buf * BBUF;

        if (it + 1 < kIters) {
            const int ko = (it + 1) * 16;
            ra = *(const float4*)(Ap + ko);
            rb = *(const float4*)(Wp + (size_t)ko * 1024);
        }

        uint32_t ah[2][4], bh[4][2];
#pragma unroll
        for (int mt = 0; mt < 2; mt++)
            ldsm4(ah[mt][0], ah[mt][1], ah[mt][2], ah[mt][3],
                  aHb + aoff + a_off + (uint32_t)(mt * 16 * 48));
#pragma unroll
        for (int p = 0; p < 2; p++) {
            uint32_t t0, t1, t2, t3;
            ldsm4t(t0, t1, t2, t3, bHb + boff + b_off + (uint32_t)(p * 32));
            bh[2 * p][0] = t0; bh[2 * p][1] = t1;
            bh[2 * p + 1][0] = t2; bh[2 * p + 1][1] = t3;
        }
#pragma unroll
        for (int mt = 0; mt < 2; mt++)
#pragma unroll
            for (int nt = 0; nt < 4; nt++)
                mma16816(acc + (mt * 4 + nt) * 4, ah[mt], bh[nt]);

        uint32_t bl[4][2];
#pragma unroll
        for (int p = 0; p < 2; p++) {
            uint32_t t0, t1, t2, t3;
            ldsm4t(t0, t1, t2, t3, bLb + boff + b_off + (uint32_t)(p * 32));
            bl[2 * p][0] = t0; bl[2 * p][1] = t1;
            bl[2 * p + 1][0] = t2; bl[2 * p + 1][1] = t3;
        }
#pragma unroll
        for (int mt = 0; mt < 2; mt++)
#pragma unroll
            for (int nt = 0; nt < 4; nt++)
                mma16816(acc + (mt * 4 + nt) * 4, ah[mt], bl[nt]);

        uint32_t al[2][4];
#pragma unroll
        for (int mt = 0; mt < 2; mt++)
            ldsm4(al[mt][0], al[mt][1], al[mt][2], al[mt][3],
                  aLb + aoff + a_off + (uint32_t)(mt * 16 * 48));
#pragma unroll
        for (int mt = 0; mt < 2; mt++)
#pragma unroll
            for (int nt = 0; nt < 4; nt++)
                mma16816(acc + (mt * 4 + nt) * 4, al[mt], bh[nt]);

        if (it + 1 < kIters) {
            const uint32_t nb = (buf ^ 1u);
            split_store(aH, aL, nb * ABUF + stA, ra);
            split_store(bH, bL, nb * BBUF + stB, rb);
        }
        __syncthreads();
    }
}

__device__ __forceinline__ void epilogue_bias512(const float* __restrict__ acc,
                                                 const float* __restrict__ bias,
                                                 float* __restrict__ out,
                                                 int m0, int n0)
{
    const int lane = threadIdx.x & 31, wid = threadIdx.x >> 5;
    const int warp_n = wid & 3, warp_m = wid >> 2;
    const int rbase = m0 + warp_m * 32 + (lane >> 2);
    const int cbase = n0 + warp_n * 32 + (lane & 3) * 2;
#pragma unroll
    for (int mt = 0; mt < 2; mt++)
#pragma unroll
        for (int nt = 0; nt < 4; nt++) {
            const float* a = acc + (mt * 4 + nt) * 4;
            const int r = rbase + mt * 16;
            const int c = cbase + nt * 8;
            float2 b2 = *(const float2*)(bias + c);
            *(float2*)(out + (size_t)r * 1024 + c) = make_float2(a[0] + b2.x, a[1] + b2.y);
            *(float2*)(out + (size_t)(r + 8) * 1024 + c) = make_float2(a[2] + b2.x, a[3] + b2.y);
        }
}

// ============================================================================
// Merged Q/K/V projection: grid (24, 32), 512 threads
// ============================================================================
__global__ __launch_bounds__(512, 1)
void proj_qkv(const float* __restrict__ q, const float* __restrict__ k,
              const float* __restrict__ v,
              const float* __restrict__ Wq, const float* __restrict__ Wk,
              const float* __restrict__ Wv,
              const float* __restrict__ bq, const float* __restrict__ bk,
              const float* __restrict__ bv,
              float* __restrict__ qc, float* __restrict__ kc, float* __restrict__ vc)
{
    const int seg = blockIdx.x >> 3;
    const int n0 = (blockIdx.x & 7) * 128;
    const int m0 = blockIdx.y * 128;
    const float* A = (seg == 0) ? q : (seg == 1) ? k : v;
    const float* W = (seg == 0) ? Wq : (seg == 1) ? Wk : Wv;
    const float* bias = (seg == 0) ? bq : (seg == 1) ? bk : bv;
    float* out = (seg == 0) ? qc : (seg == 1) ? kc : vc;

    float acc[32];
#pragma unroll
    for (int i = 0; i < 32; i++) acc[i] = 0.0f;
    gemm_nn512(A, W, m0, n0, 64, acc);
    epilogue_bias512(acc, bias, out, m0, n0);
}

// Merged positional projections: grid (16, 8), 512 threads
__global__ __launch_bounds__(512, 1)
void proj_u(const float* __restrict__ pt,
            const float* __restrict__ Uq, const float* __restrict__ Uk,
            const float* __restrict__ buq, const float* __restrict__ buk,
            float* __restrict__ qp, float* __restrict__ kp)
{
    const int seg = blockIdx.x >> 3;
    const int n0 = (blockIdx.x & 7) * 128;
    const int m0 = blockIdx.y * 128;
    const float* W = (seg == 0) ? Uq : Uk;
    const float* bias = (seg == 0) ? buq : buk;
    float* out = (seg == 0) ? qp : kp;

    float acc[32];
#pragma unroll
    for (int i = 0; i < 32; i++) acc[i] = 0.0f;
    gemm_nn512(pt, W, m0, n0, 64, acc);
    epilogue_bias512(acc, bias, out, m0, n0);
}

// Output projection: grid (8, 32), 512 threads
__global__ __launch_bounds__(512, 1)
void proj_o(const float* __restrict__ ctx, const float* __restrict__ Wo,
            const float* __restrict__ bo, float* __restrict__ out)
{
    const int n0 = blockIdx.x * 128;
    const int m0 = blockIdx.y * 128;
    float acc[32];
#pragma unroll
    for (int i = 0; i < 32; i++) acc[i] = 0.0f;
    gemm_nn512(ctx, Wo, m0, n0, 64, acc);
    epilogue_bias512(acc, bo, out, m0, n0);
}

// ============================================================================
// NT bf16x3 core (fp32 in) — for pos_mma (K=64)  [R15, unchanged]
// ============================================================================
template <int BN>
__device__ __forceinline__ void gemm_bf16x3(
    const float* __restrict__ A, int lda, int m0,
    const float* __restrict__ Bt, int ldb, int n0,
    int kIters, float* __restrict__ acc)
{
    constexpr int NWN = BN / 32;
    constexpr int NWM = 8 / NWN;
    constexpr int WROWS = 128 / NWM;
    constexpr int MT = WROWS / 16;

    __shared__ __align__(16) __nv_bfloat16 sAh[128][24];
    __shared__ __align__(16) __nv_bfloat16 sAl[128][24];
    __shared__ __align__(16) __nv_bfloat16 sBh[BN][24];
    __shared__ __align__(16) __nv_bfloat16 sBl[BN][24];

    const int tid = threadIdx.x;
    const int lane = tid & 31;
    const int wid = tid >> 5;
    const int warp_n = wid % NWN;
    const int warp_m = wid / NWN;

    const int row0 = tid >> 2;
    const int c0 = tid & 3;

    const float* ApA = A + (size_t)(m0 + row0) * lda + c0 * 4;
    const float* ApB = ApA + (size_t)64 * lda;
    const float* BpA = Bt + (size_t)(n0 + row0) * ldb + c0 * 4;
    const float* BpB = BpA + (size_t)64 * ldb;

    const uint32_t stA = (uint32_t)row0 * 48u + (uint32_t)c0 * 8u;
    const uint32_t stB = stA + 64u * 48u;

    const uint32_t baseAh = smem_u32(sAh);
    const uint32_t baseAl = smem_u32(sAl);
    const uint32_t baseBh = smem_u32(sBh);
    const uint32_t baseBl = smem_u32(sBl);

    const uint32_t a_off =
        (uint32_t)((warp_m * WROWS + (lane & 7) + ((lane >> 3) & 1) * 8) * 48 +
                   (lane >> 4) * 16);
    const uint32_t b_off =
        (uint32_t)((warp_n * 32 + (lane & 7) + ((lane >> 4) & 1) * 8) * 48 +
                   ((lane >> 3) & 1) * 16);

    float4 ra0 = *(const float4*)ApA;
    float4 ra1 = *(const float4*)ApB;
    float4 rb0 = *(const float4*)BpA;
    float4 rb1 = make_float4(0.f, 0.f, 0.f, 0.f);
    if (BN == 128) rb1 = *(const float4*)BpB;

    for (int it = 0; it < kIters; ++it) {
        __syncthreads();
        split_store((char*)sAh, (char*)sAl, stA, ra0);
        split_store((char*)sAh, (char*)sAl, stB, ra1);
        split_store((char*)sBh, (char*)sBl, stA, rb0);
        if (BN == 128) split_store((char*)sBh, (char*)sBl, stB, rb1);
        __syncthreads();

        if (it + 1 < kIters) {
            const int ko = (it + 1) * 16;
            ra0 = *(const float4*)(ApA + ko);
            ra1 = *(const float4*)(ApB + ko);
            rb0 = *(const float4*)(BpA + ko);
            if (BN == 128) rb1 = *(const float4*)(BpB + ko);
        }

        uint32_t ah[MT][4], bh[4][2];
#pragma unroll
        for (int mt = 0; mt < MT; mt++)
            ldsm4(ah[mt][0], ah[mt][1], ah[mt][2], ah[mt][3],
                  baseAh + a_off + (uint32_t)(mt * 16 * 48));
#pragma unroll
        for (int p = 0; p < 2; p++) {
            uint32_t t0, t1, t2, t3;
            ldsm4(t0, t1, t2, t3, baseBh + b_off + (uint32_t)(p * 16 * 48));
            bh[2 * p][0] = t0; bh[2 * p][1] = t1;
            bh[2 * p + 1][0] = t2; bh[2 * p + 1][1] = t3;
        }
#pragma unroll
        for (int mt = 0; mt < MT; mt++)
#pragma unroll
            for (int nt = 0; nt < 4; nt++)
                mma16816(acc + (mt * 4 + nt) * 4, ah[mt], bh[nt]);

        uint32_t bl[4][2];
#pragma unroll
        for (int p = 0; p < 2; p++) {
            uint32_t t0, t1, t2, t3;
            ldsm4(t0, t1, t2, t3, baseBl + b_off + (uint32_t)(p * 16 * 48));
            bl[2 * p][0] = t0; bl[2 * p][1] = t1;
            bl[2 * p + 1][0] = t2; bl[2 * p + 1][1] = t3;
        }
#pragma unroll
        for (int mt = 0; mt < MT; mt++)
#pragma unroll
            for (int nt = 0; nt < 4; nt++)
                mma16816(acc + (mt * 4 + nt) * 4, ah[mt], bl[nt]);

        uint32_t al[MT][4];
#pragma unroll
        for (int mt = 0; mt < MT; mt++)
            ldsm4(al[mt][0], al[mt][1], al[mt][2], al[mt][3],
                  baseAl + a_off + (uint32_t)(mt * 16 * 48));
#pragma unroll
        for (int mt = 0; mt < MT; mt++)
#pragma unroll
            for (int nt = 0; nt < 4; nt++)
                mma16816(acc + (mt * 4 + nt) * 4, al[mt], bh[nt]);
    }
}

// ============================================================================
// pos scores: pos[h] = q_p @ k_p^T with theta patches; K=64  [R15, unchanged]
// ============================================================================
__global__ __launch_bounds__(256, 1)
void pos_mma(const float* __restrict__ qp, const float* __restrict__ kp,
             const float* __restrict__ tcc, const float* __restrict__ tco,
             const float* __restrict__ toc, float* __restrict__ pos)
{
    const int h = blockIdx.z;
    float acc[64];
#pragma unroll
    for (int i = 0; i < 64; i++) acc[i] = 0.0f;
    const int m0 = blockIdx.y * 128, n0 = blockIdx.x * 128;
    gemm_bf16x3<128>(qp + h * DEPTH, 1024, m0, kp + h * DEPTH, 1024, n0, 4, acc);

    const float thcc = tcc[h], thco = tco[h], thoc = toc[h];
    float* O = pos + (size_t)h * S_ * S_;

    const int lane = threadIdx.x & 31, wid = threadIdx.x >> 5;
    const int warp_n = wid & 3, warp_m = wid >> 2;
    const int rbase = m0 + warp_m * 64 + (lane >> 2);
    const int cbase = n0 + warp_n * 32 + (lane & 3) * 2;
#pragma unroll
    for (int mt = 0; mt < 4; mt++)
#pragma unroll
        for (int nt = 0; nt < 4; nt++) {
            const float* a = acc + (mt * 4 + nt) * 4;
            const int r = rbase + mt * 16;
            const int c = cbase + nt * 8;
            float v0 = a[0], v1 = a[1], v2 = a[2], v3 = a[3];
            if (r == 0) { v0 = (c == 0) ? thcc : thco; v1 = thco; }
            else if (c == 0) v0 = thoc;
            if (c == 0) v2 = thoc;
            *(float2*)(O + (size_t)r * 1024 + c) = make_float2(v0, v1);
            *(float2*)(O + (size_t)(r + 8) * 1024 + c) = make_float2(v2, v3);
        }
}

// ============================================================================
// Fused flash attention  [R15, unchanged]
// ============================================================================
#define QK_STRIDE 144
#define VT_STRIDE 272
#define QH_OFF 0
#define QL_OFF 18432
#define KH_OFF 36864
#define KL_OFF 55296
#define VH_OFF 73728
#define VL_OFF 91136
#define RS_OFF 108544
#define FLASH_SMEM 110592

__global__ __launch_bounds__(256, 1)
void flash_attn(const float* __restrict__ qc, const float* __restrict__ kc,
                const float* __restrict__ vt, const float* __restrict__ pos,
                float* __restrict__ ctx)
{
    extern __shared__ char sm[];
    char* qh = sm + QH_OFF;  char* ql = sm + QL_OFF;
    char* kh = sm + KH_OFF;  char* kl = sm + KL_OFF;
    char* vh = sm + VH_OFF;  char* vl = sm + VL_OFF;
    float* rsum_sm = (float*)(sm + RS_OFF);

    const int bh = blockIdx.y;
    const int b = bh >> 4, h = bh & 15;
    const int m0 = blockIdx.x * 128;

    const int tid = threadIdx.x;
    const int lane = tid & 31;
    const int wid = tid >> 5;
    const int warp_m = wid >> 2;
    const int warp_n = wid & 3;

    const float* Qb = qc + ((size_t)b * S_ + m0) * D_MODEL + h * DEPTH;
    const float* Kb = kc + (size_t)b * S_ * D_MODEL + h * DEPTH;
    const float* Vb = vt + (size_t)bh * DEPTH * S_;
    const float* Pb = pos + (size_t)h * S_ * S_;

    const uint32_t qh_b = smem_u32(qh), ql_b = smem_u32(ql);
    const uint32_t kh_b = smem_u32(kh), kl_b = smem_u32(kl);
    const uint32_t vh_b = smem_u32(vh), vl_b = smem_u32(vl);

    const int row0 = tid >> 2;
    const int c0 = tid & 3;

#pragma unroll
    for (int kcix = 0; kcix < 4; kcix++) {
        float4 v0 = *(const float4*)(Qb + (size_t)row0 * 1024 + kcix * 16 + c0 * 4);
        float4 v1 = *(const float4*)(Qb + (size_t)(row0 + 64) * 1024 + kcix * 16 + c0 * 4);
        split_store(qh, ql, (uint32_t)row0 * QK_STRIDE + kcix * 32 + c0 * 8, v0);
        split_store(qh, ql, (uint32_t)(row0 + 64) * QK_STRIDE + kcix * 32 + c0 * 8, v1);
    }

    const uint32_t a_off =
        (uint32_t)((warp_m * 64 + (lane & 7) + ((lane >> 3) & 1) * 8) * QK_STRIDE +
                   (lane >> 4) * 16);
    const uint32_t b_off =
        (uint32_t)((warp_n * 32 + (lane & 7) + ((lane >> 4) & 1) * 8) * QK_STRIDE +
                   ((lane >> 3) & 1) * 16);
    const uint32_t bv_off =
        (uint32_t)((warp_n * 16 + (lane & 7) + ((lane >> 4) & 1) * 8) * VT_STRIDE +
                   ((lane >> 3) & 1) * 16);

    const int rbase = warp_m * 64 + (lane >> 2);
    const int cbase = warp_n * 32 + (lane & 3) * 2;
    const int khalf = warp_n >> 1;
    const int clocal = (warp_n & 1) * 32 + (lane & 3) * 2;

    float oacc[32];
#pragma unroll
    for (int i = 0; i < 32; i++) oacc[i] = 0.0f;
    float rs[8];
#pragma unroll
    for (int i = 0; i < 8; i++) rs[i] = 0.0f;

    for (int j = 0; j < 8; ++j) {
        __syncthreads();

#pragma unroll
        for (int kcix = 0; kcix < 4; kcix++) {
            float4 v0 = *(const float4*)(Kb + (size_t)(j * 128 + row0) * 1024 + kcix * 16 + c0 * 4);
            float4 v1 = *(const float4*)(Kb + (size_t)(j * 128 + row0 + 64) * 1024 + kcix * 16 + c0 * 4);
            split_store(kh, kl, (uint32_t)row0 * QK_STRIDE + kcix * 32 + c0 * 8, v0);
            split_store(kh, kl, (uint32_t)(row0 + 64) * QK_STRIDE + kcix * 32 + c0 * 8, v1);
        }
#pragma unroll
        for (int cc = 0; cc < 8; cc++) {
            float4 v0 = *(const float4*)(Vb + (size_t)row0 * S_ + j * 128 + cc * 16 + c0 * 4);
            split_store(vh, vl, (uint32_t)row0 * VT_STRIDE + cc * 32 + c0 * 8, v0);
        }
        __syncthreads();

        float sacc[64];
#pragma unroll
        for (int i = 0; i < 64; i++) sacc[i] = 0.0f;

        for (int ki = 0; ki < 4; ++ki) {
            const uint32_t ko = (uint32_t)(ki * 32);
            uint32_t ah[4][4], bhf[4][2];
#pragma unroll
            for (int mt = 0; mt < 4; mt++)
                ldsm4(ah[mt][0], ah[mt][1], ah[mt][2], ah[mt][3],
                      qh_b + a_off + (uint32_t)(mt * 16 * QK_STRIDE) + ko);
#pragma unroll
            for (int p = 0; p < 2; p++) {
                uint32_t t0, t1, t2, t3;
                ldsm4(t0, t1, t2, t3, kh_b + b_off + (uint32_t)(p * 16 * QK_STRIDE) + ko);
                bhf[2 * p][0] = t0; bhf[2 * p][1] = t1;
                bhf[2 * p + 1][0] = t2; bhf[2 * p + 1][1] = t3;
            }
#pragma unroll
            for (int mt = 0; mt < 4; mt++)
#pragma unroll
                for (int nt = 0; nt < 4; nt++)
                    mma16816(sacc + (mt * 4 + nt) * 4, ah[mt], bhf[nt]);

            uint32_t blf[4][2];
#pragma unroll
            for (int p = 0; p < 2; p++) {
                uint32_t t0, t1, t2, t3;
                ldsm4(t0, t1, t2, t3, kl_b + b_off + (uint32_t)(p * 16 * QK_STRIDE) + ko);
                blf[2 * p][0] = t0; blf[2 * p][1] = t1;
                blf[2 * p + 1][0] = t2; blf[2 * p + 1][1] = t3;
            }
#pragma unroll
            for (int mt = 0; mt < 4; mt++)
#pragma unroll
                for (int nt = 0; nt < 4; nt++)
                    mma16816(sacc + (mt * 4 + nt) * 4, ah[mt], blf[nt]);

            uint32_t al[4][4];
#pragma unroll
            for (int mt = 0; mt < 4; mt++)
                ldsm4(al[mt][0], al[mt][1], al[mt][2], al[mt][3],
                      ql_b + a_off + (uint32_t)(mt * 16 * QK_STRIDE) + ko);
#pragma unroll
            for (int mt = 0; mt < 4; mt++)
#pragma unroll
                for (int nt = 0; nt < 4; nt++)
                    mma16816(sacc + (mt * 4 + nt) * 4, al[mt], bhf[nt]);
        }

#pragma unroll
        for (int mt = 0; mt < 4; mt++) {
            const int r = rbase + mt * 16;
#pragma unroll
            for (int nt = 0; nt < 4; nt++) {
                float* a = sacc + (mt * 4 + nt) * 4;
                const int cg = j * 128 + cbase + nt * 8;
                float2 p0 = *(const float2*)(Pb + (size_t)(m0 + r) * 1024 + cg);
                float2 p1 = *(const float2*)(Pb + (size_t)(m0 + r + 8) * 1024 + cg);
                a[0] = __expf((a[0] + p0.x) * 0.125f);
                a[1] = __expf((a[1] + p0.y) * 0.125f);
                a[2] = __expf((a[2] + p1.x) * 0.125f);
                a[3] = __expf((a[3] + p1.y) * 0.125f);
                rs[mt * 2 + 0] += a[0] + a[1];
                rs[mt * 2 + 1] += a[2] + a[3];
            }
        }

#pragma unroll
        for (int half = 0; half < 2; ++half) {
            __syncthreads();
            if (khalf == half) {
#pragma unroll
                for (int mt = 0; mt < 4; mt++) {
                    const int r = rbase + mt * 16;
#pragma unroll
                    for (int nt = 0; nt < 4; nt++) {
                        float* a = sacc + (mt * 4 + nt) * 4;
                        const uint32_t co = (uint32_t)(clocal + nt * 8) * 2u;
                        uint32_t hi, lo;
                        split_pair(a[0], a[1], hi, lo);
                        *(uint32_t*)(kh + (uint32_t)r * QK_STRIDE + co) = hi;
                        *(uint32_t*)(kl + (uint32_t)r * QK_STRIDE + co) = lo;
                        split_pair(a[2], a[3], hi, lo);
                        *(uint32_t*)(kh + (uint32_t)(r + 8) * QK_STRIDE + co) = hi;
                        *(uint32_t*)(kl + (uint32_t)(r + 8) * QK_STRIDE + co) = lo;
                    }
                }
            }
            __syncthreads();

            const uint32_t vcol = (uint32_t)(half * 128);
            for (int ki = 0; ki < 4; ++ki) {
                const uint32_t ko = (uint32_t)(ki * 32);
                uint32_t pa[4][4], vbh[2][2], vbl[2][2];
#pragma unroll
                for (int mt = 0; mt < 4; mt++)
                    ldsm4(pa[mt][0], pa[mt][1], pa[mt][2], pa[mt][3],
                          kh_b + a_off + (uint32_t)(mt * 16 * QK_STRIDE) + ko);
                {
                    uint32_t t0, t1, t2, t3;
                    ldsm4(t0, t1, t2, t3, vh_b + bv_off + vcol + ko);
                    vbh[0][0] = t0; vbh[0][1] = t1; vbh[1][0] = t2; vbh[1][1] = t3;
                    ldsm4(t0, t1, t2, t3, vl_b + bv_off + vcol + ko);
                    vbl[0][0] = t0; vbl[0][1] = t1; vbl[1][0] = t2; vbl[1][1] = t3;
                }
#pragma unroll
                for (int mt = 0; mt < 4; mt++)
#pragma unroll
                    for (int nt = 0; nt < 2; nt++) {
                        mma16816(oacc + (mt * 2 + nt) * 4, pa[mt], vbh[nt]);
                        mma16816(oacc + (mt * 2 + nt) * 4, pa[mt], vbl[nt]);
                    }
                uint32_t pl[4][4];
#pragma unroll
                for (int mt = 0; mt < 4; mt++)
                    ldsm4(pl[mt][0], pl[mt][1], pl[mt][2], pl[mt][3],
                          kl_b + a_off + (uint32_t)(mt * 16 * QK_STRIDE) + ko);
#pragma unroll
                for (int mt = 0; mt < 4; mt++)
#pragma unroll
                    for (int nt = 0; nt < 2; nt++)
                        mma16816(oacc + (mt * 2 + nt) * 4, pl[mt], vbh[nt]);
            }
        }
    }

#pragma unroll
    for (int i = 0; i < 8; i++) {
        rs[i] += __shfl_xor_sync(0xffffffffu, rs[i], 1);
        rs[i] += __shfl_xor_sync(0xffffffffu, rs[i], 2);
    }
    if ((lane & 3) == 0) {
#pragma unroll
        for (int mt = 0; mt < 4; mt++) {
            rsum_sm[warp_n * 128 + rbase + mt * 16] = rs[mt * 2 + 0];
            rsum_sm[warp_n * 128 + rbase + mt * 16 + 8] = rs[mt * 2 + 1];
        }
    }
    __syncthreads();

    float* Ob = ctx + ((size_t)b * S_ + m0) * D_MODEL + h * DEPTH;
    const int cob = warp_n * 16 + (lane & 3) * 2;
#pragma unroll
    for (int mt = 0; mt < 4; mt++) {
        const int r = rbase + mt * 16;
        const float inv0 = 1.0f / (rsum_sm[r] + rsum_sm[128 + r] +
                                   rsum_sm[256 + r] + rsum_sm[384 + r]);
        const float inv1 = 1.0f / (rsum_sm[r + 8] + rsum_sm[128 + r + 8] +
                                   rsum_sm[256 + r + 8] + rsum_sm[384 + r + 8]);
#pragma unroll
        for (int nt = 0; nt < 2; nt++) {
            const float* a = oacc + (mt * 2 + nt) * 4;
            const int c = cob + nt * 8;
            *(float2*)(Ob + (size_t)r * 1024 + c) = make_float2(a[0] * inv0, a[1] * inv0);
            *(float2*)(Ob + (size_t)(r + 8) * 1024 + c) = make_float2(a[2] * inv1, a[3] * inv1);
        }
    }
}

// ============================================================================
// V transpose (fp32)  [R15, unchanged]
// ============================================================================
__global__ __launch_bounds__(256)
void transpose_v(const float* __restrict__ vc, float* __restrict__ vt) {
    __shared__ float t[32][33];
    const int bh = blockIdx.z;
    const int b = bh >> 4, h = bh & 15;
    const int s0 = blockIdx.x * 32, d0 = blockIdx.y * 32;
    const int txx = threadIdx.x, tyy = threadIdx.y;
#pragma unroll
    for (int i = tyy; i < 32; i += 8)
        t[i][txx] = vc[((size_t)b * S_ + s0 + i) * D_MODEL + h * DEPTH + d0 + txx];
    __syncthreads();
#pragma unroll
    for (int i = tyy; i < 32; i += 8)
        vt[(size_t)bh * DEPTH * S_ + (size_t)(d0 + i) * S_ + s0 + txx] = t[txx][i];
}

// ============================================================================
// kernel_launch
// ============================================================================
extern "C" void kernel_launch(void* const* d_in, const int* in_sizes, int n_in,
                              void* d_out, int out_size)
{
    (void)in_sizes; (void)n_in; (void)out_size;

    const float* q   = (const float*)d_in[0];
    const float* k   = (const float*)d_in[1];
    const float* v   = (const float*)d_in[2];
    const float* Wq  = (const float*)d_in[3];
    const float* bq  = (const float*)d_in[4];
    const float* Wk  = (const float*)d_in[5];
    const float* bk  = (const float*)d_in[6];
    const float* Wv  = (const float*)d_in[7];
    const float* bv  = (const float*)d_in[8];
    const float* Uq  = (const float*)d_in[9];
    const float* buq = (const float*)d_in[10];
    const float* Uk  = (const float*)d_in[11];
    const float* buk = (const float*)d_in[12];
    const float* pt  = (const float*)d_in[13];
    const float* tcc = (const float*)d_in[14];
    const float* tco = (const float*)d_in[15];
    const float* toc = (const float*)d_in[16];
    const float* Wo  = (const float*)d_in[17];
    const float* bo  = (const float*)d_in[18];
    float* out = (float*)d_out;

    float *qc, *kc, *vc, *qp, *kp, *pos, *ctx, *vt;
    cudaGetSymbolAddress((void**)&qc, g_qc);
    cudaGetSymbolAddress((void**)&kc, g_kc);
    cudaGetSymbolAddress((void**)&vc, g_vc);
    cudaGetSymbolAddress((void**)&qp, g_qp);
    cudaGetSymbolAddress((void**)&kp, g_kp);
    cudaGetSymbolAddress((void**)&pos, g_pos);
    cudaGetSymbolAddress((void**)&ctx, g_ctx);
    cudaGetSymbolAddress((void**)&vt, g_vt);

    cudaFuncSetAttribute(flash_attn,
                         cudaFuncAttributeMaxDynamicSharedMemorySize, FLASH_SMEM);

    // Q/K/V projections in one launch (512 threads, 16 warps/CTA)
    proj_qkv<<<dim3(24, 32), 512>>>(q, k, v, Wq, Wk, Wv, bq, bk, bv, qc, kc, vc);

    // positional projections in one launch
    proj_u<<<dim3(16, 8), 512>>>(pt, Uq, Uk, buq, buk, qp, kp);

    // V^T per head
    transpose_v<<<dim3(S_ / 32, DEPTH / 32, B_ * NUM_HEADS), dim3(32, 8)>>>(vc, vt);

    // pos scores (theta patches fused)
    pos_mma<<<dim3(8, 8, NUM_HEADS), 256>>>(qp, kp, tcc, tco, toc, pos);

    // fused scores + softmax + AV
    flash_attn<<<dim3(8, 64), 256, FLASH_SMEM>>>(qc, kc, vt, pos, ctx);

    // output projection
    proj_o<<<dim3(8, 32), 512>>>(ctx, Wo, bo, out);
}

// round 17
// speedup vs baseline: 1.4582x; 1.0240x over previous
#include <cuda_runtime.h>
#include <cuda_bf16.h>
#include <math.h>
#include <stdint.h>

#define D_MODEL 1024
#define NUM_HEADS 16
#define DEPTH 64
#define B_ 4
#define S_ 1024

// ---------------- scratch (static device globals; no allocation) -------------
__device__ float g_qc[(size_t)B_ * S_ * D_MODEL];            // 16 MB
__device__ float g_kc[(size_t)B_ * S_ * D_MODEL];            // 16 MB
__device__ float g_vc[(size_t)B_ * S_ * D_MODEL];            // 16 MB
__device__ float g_qp[(size_t)S_ * D_MODEL];                 // 4 MB
__device__ float g_kp[(size_t)S_ * D_MODEL];                 // 4 MB
__device__ float g_pos[(size_t)NUM_HEADS * S_ * S_];         // 64 MB
__device__ float g_ctx[(size_t)B_ * S_ * D_MODEL];           // 16 MB
__device__ float g_vt[(size_t)B_ * NUM_HEADS * DEPTH * S_];  // 16 MB (V^T per head)

// ============================================================================
// mma.sync helpers
// ============================================================================
__device__ __forceinline__ uint32_t smem_u32(const void* p) {
    uint32_t a;
    asm("{ .reg .u64 t; cvta.to.shared.u64 t, %1; cvt.u32.u64 %0, t; }" : "=r"(a) : "l"(p));
    return a;
}

__device__ __forceinline__ void ldsm4(uint32_t& r0, uint32_t& r1, uint32_t& r2,
                                      uint32_t& r3, uint32_t addr) {
    asm volatile("ldmatrix.sync.aligned.m8n8.x4.shared.b16 {%0,%1,%2,%3}, [%4];"
                 : "=r"(r0), "=r"(r1), "=r"(r2), "=r"(r3) : "r"(addr));
}

__device__ __forceinline__ void ldsm4t(uint32_t& r0, uint32_t& r1, uint32_t& r2,
                                       uint32_t& r3, uint32_t addr) {
    asm volatile("ldmatrix.sync.aligned.m8n8.x4.trans.shared.b16 {%0,%1,%2,%3}, [%4];"
                 : "=r"(r0), "=r"(r1), "=r"(r2), "=r"(r3) : "r"(addr));
}

__device__ __forceinline__ void mma16816(float* c, const uint32_t* a, const uint32_t* b) {
    asm volatile("mma.sync.aligned.m16n8k16.row.col.f32.bf16.bf16.f32 "
                 "{%0,%1,%2,%3}, {%4,%5,%6,%7}, {%8,%9}, {%0,%1,%2,%3};"
                 : "+f"(c[0]), "+f"(c[1]), "+f"(c[2]), "+f"(c[3])
                 : "r"(a[0]), "r"(a[1]), "r"(a[2]), "r"(a[3]), "r"(b[0]), "r"(b[1]));
}

__device__ __forceinline__ void split_pair(float x, float y, uint32_t& hi, uint32_t& lo) {
    __nv_bfloat162 h = __floats2bfloat162_rn(x, y);
    float hx = __bfloat162float(h.x);
    float hy = __bfloat162float(h.y);
    __nv_bfloat162 l = __floats2bfloat162_rn(x - hx, y - hy);
    hi = *reinterpret_cast<uint32_t*>(&h);
    lo = *reinterpret_cast<uint32_t*>(&l);
}

__device__ __forceinline__ void split_store(char* sH, char* sL, uint32_t off, float4 v) {
    uint32_t h0, l0, h1, l1;
    split_pair(v.x, v.y, h0, l0);
    split_pair(v.z, v.w, h1, l1);
    *(uint2*)(sH + off) = make_uint2(h0, h1);
    *(uint2*)(sL + off) = make_uint2(l0, l1);
}

// ============================================================================
// NN bf16x3 GEMM core, 512 threads (16 warps = 4 warps/SMSP)  [R16, unchanged]
// ============================================================================
__device__ __forceinline__ void gemm_nn512(const float* __restrict__ A,
                                           const float* __restrict__ W,
                                           int m0, int n0, int kIters,
                                           float* __restrict__ acc /*32*/)
{
    __shared__ __align__(16) __nv_bfloat16 sAh[2][128][24];
    __shared__ __align__(16) __nv_bfloat16 sAl[2][128][24];
    __shared__ __align__(16) __nv_bfloat16 sBh[2][16][136];
    __shared__ __align__(16) __nv_bfloat16 sBl[2][16][136];

    const int tid = threadIdx.x;
    const int lane = tid & 31, wid = tid >> 5;
    const int warp_n = wid & 3, warp_m = wid >> 2;

    const int rowA = tid >> 2, cA = tid & 3;
    const int rowB = tid >> 5, cB = (tid & 31) * 4;

    const float* Ap = A + (size_t)(m0 + rowA) * 1024 + cA * 4;
    const float* Wp = W + (size_t)rowB * 1024 + n0 + cB;

    const uint32_t stA = (uint32_t)rowA * 48u + (uint32_t)cA * 8u;
    const uint32_t stB = (uint32_t)rowB * 272u + (uint32_t)cB * 2u;

    char* aH = (char*)sAh; char* aL = (char*)sAl;
    char* bH = (char*)sBh; char* bL = (char*)sBl;
    const uint32_t aHb = smem_u32(sAh), aLb = smem_u32(sAl);
    const uint32_t bHb = smem_u32(sBh), bLb = smem_u32(sBl);
    const uint32_t ABUF = 128u * 48u;
    const uint32_t BBUF = 16u * 272u;

    const uint32_t a_off =
        (uint32_t)((warp_m * 32 + (lane & 7) + ((lane >> 3) & 1) * 8) * 48 +
                   (lane >> 4) * 16);
    const uint32_t b_off =
        (uint32_t)(((lane & 7) + ((lane >> 3) & 1) * 8) * 272 +
                   (warp_n * 32 + ((lane >> 4) & 1) * 8) * 2);

    float4 ra = *(const float4*)Ap;
    float4 rb = *(const float4*)Wp;

    split_store(aH, aL, stA, ra);
    split_store(bH, bL, stB, rb);
    __syncthreads();

    for (int it = 0; it < kIters; ++it) {
        const uint32_t buf = (uint32_t)(it & 1);
        const uint32_t aoff = buf * ABUF, boff = buf * BBUF;

        if (it + 1 < kIters) {
            const int ko = (it + 1) * 16;
            ra = *(const float4*)(Ap + ko);
            rb = *(const float4*)(Wp + (size_t)ko * 1024);
        }

        uint32_t ah[2][4], bh[4][2];
#pragma unroll
        for (int mt = 0; mt < 2; mt++)
            ldsm4(ah[mt][0], ah[mt][1], ah[mt][2], ah[mt][3],
                  aHb + aoff + a_off + (uint32_t)(mt * 16 * 48));
#pragma unroll
        for (int p = 0; p < 2; p++) {
            uint32_t t0, t1, t2, t3;
            ldsm4t(t0, t1, t2, t3, bHb + boff + b_off + (uint32_t)(p * 32));
            bh[2 * p][0] = t0; bh[2 * p][1] = t1;
            bh[2 * p + 1][0] = t2; bh[2 * p + 1][1] = t3;
        }
#pragma unroll
        for (int mt = 0; mt < 2; mt++)
#pragma unroll
            for (int nt = 0; nt < 4; nt++)
                mma16816(acc + (mt * 4 + nt) * 4, ah[mt], bh[nt]);

        uint32_t bl[4][2];
#pragma unroll
        for (int p = 0; p < 2; p++) {
            uint32_t t0, t1, t2, t3;
            ldsm4t(t0, t1, t2, t3, bLb + boff + b_off + (uint32_t)(p * 32));
            bl[2 * p][0] = t0; bl[2 * p][1] = t1;
            bl[2 * p + 1][0] = t2; bl[2 * p + 1][1] = t3;
        }
#pragma unroll
        for (int mt = 0; mt < 2; mt++)
#pragma unroll
            for (int nt = 0; nt < 4; nt++)
                mma16816(acc + (mt * 4 + nt) * 4, ah[mt], bl[nt]);

        uint32_t al[2][4];
#pragma unroll
        for (int mt = 0; mt < 2; mt++)
            ldsm4(al[mt][0], al[mt][1], al[mt][2], al[mt][3],
                  aLb + aoff + a_off + (uint32_t)(mt * 16 * 48));
#pragma unroll
        for (int mt = 0; mt < 2; mt++)
#pragma unroll
            for (int nt = 0; nt < 4; nt++)
                mma16816(acc + (mt * 4 + nt) * 4, al[mt], bh[nt]);

        if (it + 1 < kIters) {
            const uint32_t nb = (buf ^ 1u);
            split_store(aH, aL, nb * ABUF + stA, ra);
            split_store(bH, bL, nb * BBUF + stB, rb);
        }
        __syncthreads();
    }
}

__device__ __forceinline__ void epilogue_bias512(const float* __restrict__ acc,
                                                 const float* __restrict__ bias,
                                                 float* __restrict__ out,
                                                 int m0, int n0)
{
    const int lane = threadIdx.x & 31, wid = threadIdx.x >> 5;
    const int warp_n = wid & 3, warp_m = wid >> 2;
    const int rbase = m0 + warp_m * 32 + (lane >> 2);
    const int cbase = n0 + warp_n * 32 + (lane & 3) * 2;
#pragma unroll
    for (int mt = 0; mt < 2; mt++)
#pragma unroll
        for (int nt = 0; nt < 4; nt++) {
            const float* a = acc + (mt * 4 + nt) * 4;
            const int r = rbase + mt * 16;
            const int c = cbase + nt * 8;
            float2 b2 = *(const float2*)(bias + c);
            *(float2*)(out + (size_t)r * 1024 + c) = make_float2(a[0] + b2.x, a[1] + b2.y);
            *(float2*)(out + (size_t)(r + 8) * 1024 + c) = make_float2(a[2] + b2.x, a[3] + b2.y);
        }
}

// ============================================================================
// Merged Q/K/V projection  [R16, unchanged]
// ============================================================================
__global__ __launch_bounds__(512, 1)
void proj_qkv(const float* __restrict__ q, const float* __restrict__ k,
              const float* __restrict__ v,
              const float* __restrict__ Wq, const float* __restrict__ Wk,
              const float* __restrict__ Wv,
              const float* __restrict__ bq, const float* __restrict__ bk,
              const float* __restrict__ bv,
              float* __restrict__ qc, float* __restrict__ kc, float* __restrict__ vc)
{
    const int seg = blockIdx.x >> 3;
    const int n0 = (blockIdx.x & 7) * 128;
    const int m0 = blockIdx.y * 128;
    const float* A = (seg == 0) ? q : (seg == 1) ? k : v;
    const float* W = (seg == 0) ? Wq : (seg == 1) ? Wk : Wv;
    const float* bias = (seg == 0) ? bq : (seg == 1) ? bk : bv;
    float* out = (seg == 0) ? qc : (seg == 1) ? kc : vc;

    float acc[32];
#pragma unroll
    for (int i = 0; i < 32; i++) acc[i] = 0.0f;
    gemm_nn512(A, W, m0, n0, 64, acc);
    epilogue_bias512(acc, bias, out, m0, n0);
}

__global__ __launch_bounds__(512, 1)
void proj_u(const float* __restrict__ pt,
            const float* __restrict__ Uq, const float* __restrict__ Uk,
            const float* __restrict__ buq, const float* __restrict__ buk,
            float* __restrict__ qp, float* __restrict__ kp)
{
    const int seg = blockIdx.x >> 3;
    const int n0 = (blockIdx.x & 7) * 128;
    const int m0 = blockIdx.y * 128;
    const float* W = (seg == 0) ? Uq : Uk;
    const float* bias = (seg == 0) ? buq : buk;
    float* out = (seg == 0) ? qp : kp;

    float acc[32];
#pragma unroll
    for (int i = 0; i < 32; i++) acc[i] = 0.0f;
    gemm_nn512(pt, W, m0, n0, 64, acc);
    epilogue_bias512(acc, bias, out, m0, n0);
}

__global__ __launch_bounds__(512, 1)
void proj_o(const float* __restrict__ ctx, const float* __restrict__ Wo,
            const float* __restrict__ bo, float* __restrict__ out)
{
    const int n0 = blockIdx.x * 128;
    const int m0 = blockIdx.y * 128;
    float acc[32];
#pragma unroll
    for (int i = 0; i < 32; i++) acc[i] = 0.0f;
    gemm_nn512(ctx, Wo, m0, n0, 64, acc);
    epilogue_bias512(acc, bo, out, m0, n0);
}

// ============================================================================
// NT bf16x3 core (fp32 in) — for pos_mma (K=64)  [R16, unchanged]
// ============================================================================
template <int BN>
__device__ __forceinline__ void gemm_bf16x3(
    const float* __restrict__ A, int lda, int m0,
    const float* __restrict__ Bt, int ldb, int n0,
    int kIters, float* __restrict__ acc)
{
    constexpr int NWN = BN / 32;
    constexpr int NWM = 8 / NWN;
    constexpr int WROWS = 128 / NWM;
    constexpr int MT = WROWS / 16;

    __shared__ __align__(16) __nv_bfloat16 sAh[128][24];
    __shared__ __align__(16) __nv_bfloat16 sAl[128][24];
    __shared__ __align__(16) __nv_bfloat16 sBh[BN][24];
    __shared__ __align__(16) __nv_bfloat16 sBl[BN][24];

    const int tid = threadIdx.x;
    const int lane = tid & 31;
    const int wid = tid >> 5;
    const int warp_n = wid % NWN;
    const int warp_m = wid / NWN;

    const int row0 = tid >> 2;
    const int c0 = tid & 3;

    const float* ApA = A + (size_t)(m0 + row0) * lda + c0 * 4;
    const float* ApB = ApA + (size_t)64 * lda;
    const float* BpA = Bt + (size_t)(n0 + row0) * ldb + c0 * 4;
    const float* BpB = BpA + (size_t)64 * ldb;

    const uint32_t stA = (uint32_t)row0 * 48u + (uint32_t)c0 * 8u;
    const uint32_t stB = stA + 64u * 48u;

    const uint32_t baseAh = smem_u32(sAh);
    const uint32_t baseAl = smem_u32(sAl);
    const uint32_t baseBh = smem_u32(sBh);
    const uint32_t baseBl = smem_u32(sBl);

    const uint32_t a_off =
        (uint32_t)((warp_m * WROWS + (lane & 7) + ((lane >> 3) & 1) * 8) * 48 +
                   (lane >> 4) * 16);
    const uint32_t b_off =
        (uint32_t)((warp_n * 32 + (lane & 7) + ((lane >> 4) & 1) * 8) * 48 +
                   ((lane >> 3) & 1) * 16);

    float4 ra0 = *(const float4*)ApA;
    float4 ra1 = *(const float4*)ApB;
    float4 rb0 = *(const float4*)BpA;
    float4 rb1 = make_float4(0.f, 0.f, 0.f, 0.f);
    if (BN == 128) rb1 = *(const float4*)BpB;

    for (int it = 0; it < kIters; ++it) {
        __syncthreads();
        split_store((char*)sAh, (char*)sAl, stA, ra0);
        split_store((char*)sAh, (char*)sAl, stB, ra1);
        split_store((char*)sBh, (char*)sBl, stA, rb0);
        if (BN == 128) split_store((char*)sBh, (char*)sBl, stB, rb1);
        __syncthreads();

        if (it + 1 < kIters) {
            const int ko = (it + 1) * 16;
            ra0 = *(const float4*)(ApA + ko);
            ra1 = *(const float4*)(ApB + ko);
            rb0 = *(const float4*)(BpA + ko);
            if (BN == 128) rb1 = *(const float4*)(BpB + ko);
        }

        uint32_t ah[MT][4], bh[4][2];
#pragma unroll
        for (int mt = 0; mt < MT; mt++)
            ldsm4(ah[mt][0], ah[mt][1], ah[mt][2], ah[mt][3],
                  baseAh + a_off + (uint32_t)(mt * 16 * 48));
#pragma unroll
        for (int p = 0; p < 2; p++) {
            uint32_t t0, t1, t2, t3;
            ldsm4(t0, t1, t2, t3, baseBh + b_off + (uint32_t)(p * 16 * 48));
            bh[2 * p][0] = t0; bh[2 * p][1] = t1;
            bh[2 * p + 1][0] = t2; bh[2 * p + 1][1] = t3;
        }
#pragma unroll
        for (int mt = 0; mt < MT; mt++)
#pragma unroll
            for (int nt = 0; nt < 4; nt++)
                mma16816(acc + (mt * 4 + nt) * 4, ah[mt], bh[nt]);

        uint32_t bl[4][2];
#pragma unroll
        for (int p = 0; p < 2; p++) {
            uint32_t t0, t1, t2, t3;
            ldsm4(t0, t1, t2, t3, baseBl + b_off + (uint32_t)(p * 16 * 48));
            bl[2 * p][0] = t0; bl[2 * p][1] = t1;
            bl[2 * p + 1][0] = t2; bl[2 * p + 1][1] = t3;
        }
#pragma unroll
        for (int mt = 0; mt < MT; mt++)
#pragma unroll
            for (int nt = 0; nt < 4; nt++)
                mma16816(acc + (mt * 4 + nt) * 4, ah[mt], bl[nt]);

        uint32_t al[MT][4];
#pragma unroll
        for (int mt = 0; mt < MT; mt++)
            ldsm4(al[mt][0], al[mt][1], al[mt][2], al[mt][3],
                  baseAl + a_off + (uint32_t)(mt * 16 * 48));
#pragma unroll
        for (int mt = 0; mt < MT; mt++)
#pragma unroll
            for (int nt = 0; nt < 4; nt++)
                mma16816(acc + (mt * 4 + nt) * 4, al[mt], bh[nt]);
    }
}

// ============================================================================
// pos scores  [R16, unchanged]
// ============================================================================
__global__ __launch_bounds__(256, 1)
void pos_mma(const float* __restrict__ qp, const float* __restrict__ kp,
             const float* __restrict__ tcc, const float* __restrict__ tco,
             const float* __restrict__ toc, float* __restrict__ pos)
{
    const int h = blockIdx.z;
    float acc[64];
#pragma unroll
    for (int i = 0; i < 64; i++) acc[i] = 0.0f;
    const int m0 = blockIdx.y * 128, n0 = blockIdx.x * 128;
    gemm_bf16x3<128>(qp + h * DEPTH, 1024, m0, kp + h * DEPTH, 1024, n0, 4, acc);

    const float thcc = tcc[h], thco = tco[h], thoc = toc[h];
    float* O = pos + (size_t)h * S_ * S_;

    const int lane = threadIdx.x & 31, wid = threadIdx.x >> 5;
    const int warp_n = wid & 3, warp_m = wid >> 2;
    const int rbase = m0 + warp_m * 64 + (lane >> 2);
    const int cbase = n0 + warp_n * 32 + (lane & 3) * 2;
#pragma unroll
    for (int mt = 0; mt < 4; mt++)
#pragma unroll
        for (int nt = 0; nt < 4; nt++) {
            const float* a = acc + (mt * 4 + nt) * 4;
            const int r = rbase + mt * 16;
            const int c = cbase + nt * 8;
            float v0 = a[0], v1 = a[1], v2 = a[2], v3 = a[3];
            if (r == 0) { v0 = (c == 0) ? thcc : thco; v1 = thco; }
            else if (c == 0) v0 = thoc;
            if (c == 0) v2 = thoc;
            *(float2*)(O + (size_t)r * 1024 + c) = make_float2(v0, v1);
            *(float2*)(O + (size_t)(r + 8) * 1024 + c) = make_float2(v2, v3);
        }
}

// ============================================================================
// Fused flash attention — 512 threads (16 warps = 4 warps/SMSP)
// Warp grid 4(m)x4(n); S warp tile 32x32; O warp tile 32x16.
// Two-half P structure preserved (P buffer holds 64 key-cols).
// ============================================================================
#define QK_STRIDE 144
#define VT_STRIDE 272
#define QH_OFF 0
#define QL_OFF 18432
#define KH_OFF 36864
#define KL_OFF 55296
#define VH_OFF 73728
#define VL_OFF 91136
#define RS_OFF 108544
#define FLASH_SMEM 110592

__global__ __launch_bounds__(512, 1)
void flash_attn(const float* __restrict__ qc, const float* __restrict__ kc,
                const float* __restrict__ vt, const float* __restrict__ pos,
                float* __restrict__ ctx)
{
    extern __shared__ char sm[];
    char* qh = sm + QH_OFF;  char* ql = sm + QL_OFF;
    char* kh = sm + KH_OFF;  char* kl = sm + KL_OFF;  // reused as P hi/lo
    char* vh = sm + VH_OFF;  char* vl = sm + VL_OFF;
    float* rsum_sm = (float*)(sm + RS_OFF);           // [4][128]

    const int bh = blockIdx.y;
    const int b = bh >> 4, h = bh & 15;
    const int m0 = blockIdx.x * 128;

    const int tid = threadIdx.x;
    const int lane = tid & 31;
    const int wid = tid >> 5;
    const int warp_m = wid >> 2;   // 0..3
    const int warp_n = wid & 3;    // 0..3

    const float* Qb = qc + ((size_t)b * S_ + m0) * D_MODEL + h * DEPTH;
    const float* Kb = kc + (size_t)b * S_ * D_MODEL + h * DEPTH;
    const float* Vb = vt + (size_t)bh * DEPTH * S_;
    const float* Pb = pos + (size_t)h * S_ * S_;

    const uint32_t qh_b = smem_u32(qh), ql_b = smem_u32(ql);
    const uint32_t kh_b = smem_u32(kh), kl_b = smem_u32(kl);
    const uint32_t vh_b = smem_u32(vh), vl_b = smem_u32(vl);

    // load geometry (512 threads)
    const int rowq = tid >> 2;            // 0..127 (Q/K rows)
    const int c0 = tid & 3;               // float4 quarter within 16-float chunk
    const int rowv = tid >> 3;            // 0..63 (Vt rows)
    const int c0v = tid & 7;

    // ---- load Q tile once ----
    {
        float4 v0 = *(const float4*)(Qb + (size_t)rowq * 1024 + c0 * 4);
        float4 v1 = *(const float4*)(Qb + (size_t)rowq * 1024 + 16 + c0 * 4);
        float4 v2 = *(const float4*)(Qb + (size_t)rowq * 1024 + 32 + c0 * 4);
        float4 v3 = *(const float4*)(Qb + (size_t)rowq * 1024 + 48 + c0 * 4);
        split_store(qh, ql, (uint32_t)rowq * QK_STRIDE + 0 + c0 * 8, v0);
        split_store(qh, ql, (uint32_t)rowq * QK_STRIDE + 32 + c0 * 8, v1);
        split_store(qh, ql, (uint32_t)rowq * QK_STRIDE + 64 + c0 * 8, v2);
        split_store(qh, ql, (uint32_t)rowq * QK_STRIDE + 96 + c0 * 8, v3);
    }

    const uint32_t a_off =
        (uint32_t)((warp_m * 32 + (lane & 7) + ((lane >> 3) & 1) * 8) * QK_STRIDE +
                   (lane >> 4) * 16);
    const uint32_t b_off =
        (uint32_t)((warp_n * 32 + (lane & 7) + ((lane >> 4) & 1) * 8) * QK_STRIDE +
                   ((lane >> 3) & 1) * 16);
    const uint32_t bv_off =
        (uint32_t)((warp_n * 16 + (lane & 7) + ((lane >> 4) & 1) * 8) * VT_STRIDE +
                   ((lane >> 3) & 1) * 16);

    const int rbase = warp_m * 32 + (lane >> 2);      // S/O local row base
    const int cbase = warp_n * 32 + (lane & 3) * 2;   // S local col base
    const int khalf = warp_n >> 1;                    // 64-key half this warp stores
    const int clocal = (warp_n & 1) * 32 + (lane & 3) * 2;

    float oacc[16];
#pragma unroll
    for (int i = 0; i < 16; i++) oacc[i] = 0.0f;
    float rs[4];
#pragma unroll
    for (int i = 0; i < 4; i++) rs[i] = 0.0f;

    for (int j = 0; j < 8; ++j) {
        __syncthreads();  // prev PV done; safe to overwrite K/P and Vt buffers

        // ---- load K chunk [128x64] + Vt chunk [64x128] ----
        {
            const size_t gr = (size_t)(j * 128 + rowq) * 1024;
            float4 v0 = *(const float4*)(Kb + gr + c0 * 4);
            float4 v1 = *(const float4*)(Kb + gr + 16 + c0 * 4);
            float4 v2 = *(const float4*)(Kb + gr + 32 + c0 * 4);
            float4 v3 = *(const float4*)(Kb + gr + 48 + c0 * 4);
            split_store(kh, kl, (uint32_t)rowq * QK_STRIDE + 0 + c0 * 8, v0);
            split_store(kh, kl, (uint32_t)rowq * QK_STRIDE + 32 + c0 * 8, v1);
            split_store(kh, kl, (uint32_t)rowq * QK_STRIDE + 64 + c0 * 8, v2);
            split_store(kh, kl, (uint32_t)rowq * QK_STRIDE + 96 + c0 * 8, v3);
        }
#pragma unroll
        for (int cc = 0; cc < 4; cc++) {
            float4 v0 = *(const float4*)(Vb + (size_t)rowv * S_ + j * 128 + cc * 32 + c0v * 4);
            split_store(vh, vl, (uint32_t)rowv * VT_STRIDE + cc * 64 + c0v * 8, v0);
        }
        __syncthreads();

        // ---- S block: Q . K^T (bf16x3), warp tile 32x32 ----
        float sacc[32];
#pragma unroll
        for (int i = 0; i < 32; i++) sacc[i] = 0.0f;

        for (int ki = 0; ki < 4; ++ki) {
            const uint32_t ko = (uint32_t)(ki * 32);
            uint32_t ah[2][4], bhf[4][2];
#pragma unroll
            for (int mt = 0; mt < 2; mt++)
                ldsm4(ah[mt][0], ah[mt][1], ah[mt][2], ah[mt][3],
                      qh_b + a_off + (uint32_t)(mt * 16 * QK_STRIDE) + ko);
#pragma unroll
            for (int p = 0; p < 2; p++) {
                uint32_t t0, t1, t2, t3;
                ldsm4(t0, t1, t2, t3, kh_b + b_off + (uint32_t)(p * 16 * QK_STRIDE) + ko);
                bhf[2 * p][0] = t0; bhf[2 * p][1] = t1;
                bhf[2 * p + 1][0] = t2; bhf[2 * p + 1][1] = t3;
            }
#pragma unroll
            for (int mt = 0; mt < 2; mt++)
#pragma unroll
                for (int nt = 0; nt < 4; nt++)
                    mma16816(sacc + (mt * 4 + nt) * 4, ah[mt], bhf[nt]);

            uint32_t blf[4][2];
#pragma unroll
            for (int p = 0; p < 2; p++) {
                uint32_t t0, t1, t2, t3;
                ldsm4(t0, t1, t2, t3, kl_b + b_off + (uint32_t)(p * 16 * QK_STRIDE) + ko);
                blf[2 * p][0] = t0; blf[2 * p][1] = t1;
                blf[2 * p + 1][0] = t2; blf[2 * p + 1][1] = t3;
            }
#pragma unroll
            for (int mt = 0; mt < 2; mt++)
#pragma unroll
                for (int nt = 0; nt < 4; nt++)
                    mma16816(sacc + (mt * 4 + nt) * 4, ah[mt], blf[nt]);

            uint32_t al[2][4];
#pragma unroll
            for (int mt = 0; mt < 2; mt++)
                ldsm4(al[mt][0], al[mt][1], al[mt][2], al[mt][3],
                      ql_b + a_off + (uint32_t)(mt * 16 * QK_STRIDE) + ko);
#pragma unroll
            for (int mt = 0; mt < 2; mt++)
#pragma unroll
                for (int nt = 0; nt < 4; nt++)
                    mma16816(sacc + (mt * 4 + nt) * 4, al[mt], bhf[nt]);
        }

        // ---- epilogue: p = exp((s + pos) * 0.125); accumulate row sums ----
#pragma unroll
        for (int mt = 0; mt < 2; mt++) {
            const int r = rbase + mt * 16;
#pragma unroll
            for (int nt = 0; nt < 4; nt++) {
                float* a = sacc + (mt * 4 + nt) * 4;
                const int cg = j * 128 + cbase + nt * 8;
                float2 p0 = *(const float2*)(Pb + (size_t)(m0 + r) * 1024 + cg);
                float2 p1 = *(const float2*)(Pb + (size_t)(m0 + r + 8) * 1024 + cg);
                a[0] = __expf((a[0] + p0.x) * 0.125f);
                a[1] = __expf((a[1] + p0.y) * 0.125f);
                a[2] = __expf((a[2] + p1.x) * 0.125f);
                a[3] = __expf((a[3] + p1.y) * 0.125f);
                rs[mt * 2 + 0] += a[0] + a[1];
                rs[mt * 2 + 1] += a[2] + a[3];
            }
        }

        // ---- two k-halves: store P half, then PV mma on it ----
#pragma unroll
        for (int half = 0; half < 2; ++half) {
            __syncthreads();  // everyone done reading K (or prev P half)
            if (khalf == half) {
#pragma unroll
                for (int mt = 0; mt < 2; mt++) {
                    const int r = rbase + mt * 16;
#pragma unroll
                    for (int nt = 0; nt < 4; nt++) {
                        float* a = sacc + (mt * 4 + nt) * 4;
                        const uint32_t co = (uint32_t)(clocal + nt * 8) * 2u;
                        uint32_t hi, lo;
                        split_pair(a[0], a[1], hi, lo);
                        *(uint32_t*)(kh + (uint32_t)r * QK_STRIDE + co) = hi;
                        *(uint32_t*)(kl + (uint32_t)r * QK_STRIDE + co) = lo;
                        split_pair(a[2], a[3], hi, lo);
                        *(uint32_t*)(kh + (uint32_t)(r + 8) * QK_STRIDE + co) = hi;
                        *(uint32_t*)(kl + (uint32_t)(r + 8) * QK_STRIDE + co) = lo;
                    }
                }
            }
            __syncthreads();

            const uint32_t vcol = (uint32_t)(half * 128);
            for (int ki = 0; ki < 4; ++ki) {
                const uint32_t ko = (uint32_t)(ki * 32);
                uint32_t pa[2][4], vbh[2][2], vbl[2][2];
#pragma unroll
                for (int mt = 0; mt < 2; mt++)
                    ldsm4(pa[mt][0], pa[mt][1], pa[mt][2], pa[mt][3],
                          kh_b + a_off + (uint32_t)(mt * 16 * QK_STRIDE) + ko);
                {
                    uint32_t t0, t1, t2, t3;
                    ldsm4(t0, t1, t2, t3, vh_b + bv_off + vcol + ko);
                    vbh[0][0] = t0; vbh[0][1] = t1; vbh[1][0] = t2; vbh[1][1] = t3;
                    ldsm4(t0, t1, t2, t3, vl_b + bv_off + vcol + ko);
                    vbl[0][0] = t0; vbl[0][1] = t1; vbl[1][0] = t2; vbl[1][1] = t3;
                }
#pragma unroll
                for (int mt = 0; mt < 2; mt++)
#pragma unroll
                    for (int nt = 0; nt < 2; nt++) {
                        mma16816(oacc + (mt * 2 + nt) * 4, pa[mt], vbh[nt]);
                        mma16816(oacc + (mt * 2 + nt) * 4, pa[mt], vbl[nt]);
                    }
                uint32_t pl[2][4];
#pragma unroll
                for (int mt = 0; mt < 2; mt++)
                    ldsm4(pl[mt][0], pl[mt][1], pl[mt][2], pl[mt][3],
                          kl_b + a_off + (uint32_t)(mt * 16 * QK_STRIDE) + ko);
#pragma unroll
                for (int mt = 0; mt < 2; mt++)
#pragma unroll
                    for (int nt = 0; nt < 2; nt++)
                        mma16816(oacc + (mt * 2 + nt) * 4, pl[mt], vbh[nt]);
            }
        }
    }

    // ---- row-sum reduce + normalize + write ----
#pragma unroll
    for (int i = 0; i < 4; i++) {
        rs[i] += __shfl_xor_sync(0xffffffffu, rs[i], 1);
        rs[i] += __shfl_xor_sync(0xffffffffu, rs[i], 2);
    }
    if ((lane & 3) == 0) {
#pragma unroll
        for (int mt = 0; mt < 2; mt++) {
            rsum_sm[warp_n * 128 + rbase + mt * 16] = rs[mt * 2 + 0];
            rsum_sm[warp_n * 128 + rbase + mt * 16 + 8] = rs[mt * 2 + 1];
        }
    }
    __syncthreads();

    float* Ob = ctx + ((size_t)b * S_ + m0) * D_MODEL + h * DEPTH;
    const int cob = warp_n * 16 + (lane & 3) * 2;
#pragma unroll
    for (int mt = 0; mt < 2; mt++) {
        const int r = rbase + mt * 16;
        const float inv0 = 1.0f / (rsum_sm[r] + rsum_sm[128 + r] +
                                   rsum_sm[256 + r] + rsum_sm[384 + r]);
        const float inv1 = 1.0f / (rsum_sm[r + 8] + rsum_sm[128 + r + 8] +
                                   rsum_sm[256 + r + 8] + rsum_sm[384 + r + 8]);
#pragma unroll
        for (int nt = 0; nt < 2; nt++) {
            const float* a = oacc + (mt * 2 + nt) * 4;
            const int c = cob + nt * 8;
            *(float2*)(Ob + (size_t)r * 1024 + c) = make_float2(a[0] * inv0, a[1] * inv0);
            *(float2*)(Ob + (size_t)(r + 8) * 1024 + c) = make_float2(a[2] * inv1, a[3] * inv1);
        }
    }
}

// ============================================================================
// V transpose (fp32)  [R16, unchanged]
// ============================================================================
__global__ __launch_bounds__(256)
void transpose_v(const float* __restrict__ vc, float* __restrict__ vt) {
    __shared__ float t[32][33];
    const int bh = blockIdx.z;
    const int b = bh >> 4, h = bh & 15;
    const int s0 = blockIdx.x * 32, d0 = blockIdx.y * 32;
    const int txx = threadIdx.x, tyy = threadIdx.y;
#pragma unroll
    for (int i = tyy; i < 32; i += 8)
        t[i][txx] = vc[((size_t)b * S_ + s0 + i) * D_MODEL + h * DEPTH + d0 + txx];
    __syncthreads();
#pragma unroll
    for (int i = tyy; i < 32; i += 8)
        vt[(size_t)bh * DEPTH * S_ + (size_t)(d0 + i) * S_ + s0 + txx] = t[txx][i];
}

// ============================================================================
// kernel_launch
// ============================================================================
extern "C" void kernel_launch(void* const* d_in, const int* in_sizes, int n_in,
                              void* d_out, int out_size)
{
    (void)in_sizes; (void)n_in; (void)out_size;

    const float* q   = (const float*)d_in[0];
    const float* k   = (const float*)d_in[1];
    const float* v   = (const float*)d_in[2];
    const float* Wq  = (const float*)d_in[3];
    const float* bq  = (const float*)d_in[4];
    const float* Wk  = (const float*)d_in[5];
    const float* bk  = (const float*)d_in[6];
    const float* Wv  = (const float*)d_in[7];
    const float* bv  = (const float*)d_in[8];
    const float* Uq  = (const float*)d_in[9];
    const float* buq = (const float*)d_in[10];
    const float* Uk  = (const float*)d_in[11];
    const float* buk = (const float*)d_in[12];
    const float* pt  = (const float*)d_in[13];
    const float* tcc = (const float*)d_in[14];
    const float* tco = (const float*)d_in[15];
    const float* toc = (const float*)d_in[16];
    const float* Wo  = (const float*)d_in[17];
    const float* bo  = (const float*)d_in[18];
    float* out = (float*)d_out;

    float *qc, *kc, *vc, *qp, *kp, *pos, *ctx, *vt;
    cudaGetSymbolAddress((void**)&qc, g_qc);
    cudaGetSymbolAddress((void**)&kc, g_kc);
    cudaGetSymbolAddress((void**)&vc, g_vc);
    cudaGetSymbolAddress((void**)&qp, g_qp);
    cudaGetSymbolAddress((void**)&kp, g_kp);
    cudaGetSymbolAddress((void**)&pos, g_pos);
    cudaGetSymbolAddress((void**)&ctx, g_ctx);
    cudaGetSymbolAddress((void**)&vt, g_vt);

    cudaFuncSetAttribute(flash_attn,
                         cudaFuncAttributeMaxDynamicSharedMemorySize, FLASH_SMEM);

    // Q/K/V projections in one launch (512 threads, 16 warps/CTA)
    proj_qkv<<<dim3(24, 32), 512>>>(q, k, v, Wq, Wk, Wv, bq, bk, bv, qc, kc, vc);

    // positional projections in one launch
    proj_u<<<dim3(16, 8), 512>>>(pt, Uq, Uk, buq, buk, qp, kp);

    // V^T per head
    transpose_v<<<dim3(S_ / 32, DEPTH / 32, B_ * NUM_HEADS), dim3(32, 8)>>>(vc, vt);

    // pos scores (theta patches fused)
    pos_mma<<<dim3(8, 8, NUM_HEADS), 256>>>(qp, kp, tcc, tco, toc, pos);

    // fused scores + softmax + AV (512 threads, 16 warps/CTA)
    flash_attn<<<dim3(8, 64), 512, FLASH_SMEM>>>(qc, kc, vt, pos, ctx);

    // output projection
    proj_o<<<dim3(8, 32), 512>>>(ctx, Wo, bo, out);
}